// round 5
// baseline (speedup 1.0000x reference)
#include <cuda_runtime.h>
#include <cuda_bf16.h>
#include <math.h>
#include <stdint.h>

// Problem constants
#define BB 4
#define SS 512
#define DD 1024
#define HH 16
#define DHH 64
#define DFF 4096
#define LL 6
#define MTOK (BB*SS)          // 2048 token rows

typedef __nv_bfloat16 bf16;

// ================= device scratch =================
__device__ float g_x  [MTOK*DD];    // residual stream fp32
__device__ bf16  g_xh [MTOK*DD],  g_xl [MTOK*DD];
__device__ float g_qkv[3*MTOK*DD];  // Q,K,V in [3][B,H,S,64]
__device__ bf16  g_avh[MTOK*DD],  g_avl[MTOK*DD];
__device__ float g_y  [MTOK*DD];
__device__ float g_x1 [MTOK*DD];
__device__ bf16  g_x1h[MTOK*DD],  g_x1l[MTOK*DD];
__device__ bf16  g_ffh[MTOK*DFF], g_ffl[MTOK*DFF];

// transposed + bf16-split weights: [N, K] K-major per layer
__device__ bf16 g_wqkvT_h[3*LL*DD*DD], g_wqkvT_l[3*LL*DD*DD];   // [3][L][N][K]
__device__ bf16 g_woT_h[LL*DD*DD],  g_woT_l[LL*DD*DD];
__device__ bf16 g_w1T_h[LL*DD*DFF], g_w1T_l[LL*DD*DFF];
__device__ bf16 g_w2T_h[LL*DFF*DD], g_w2T_l[LL*DFF*DD];
__device__ float g_bqkv[3*LL*DD];

// ================= small helpers =================
__device__ __forceinline__ uint32_t smem_u32(const void* p) {
    uint32_t a;
    asm("{ .reg .u64 t; cvta.to.shared.u64 t, %1; cvt.u32.u64 %0, t; }" : "=r"(a) : "l"(p));
    return a;
}
__device__ __forceinline__ void split_bf16(float v, bf16& h, bf16& l) {
    h = __float2bfloat16_rn(v);
    l = __float2bfloat16_rn(v - __bfloat162float(h));
}

#define CP_ASYNC16(sa, ga) \
    asm volatile("cp.async.cg.shared.global [%0], [%1], 16;" :: "r"(sa), "l"(ga) : "memory")
#define CP_COMMIT() asm volatile("cp.async.commit_group;" ::: "memory")
#define CP_WAIT1()  asm volatile("cp.async.wait_group 1;" ::: "memory")

#define LDSM_X4(r0,r1,r2,r3, addr) \
    asm volatile("ldmatrix.sync.aligned.m8n8.x4.shared.b16 {%0,%1,%2,%3}, [%4];" \
        : "=r"(r0), "=r"(r1), "=r"(r2), "=r"(r3) : "r"(addr))

#define MMA_BF16(d, a, b0, b1) \
    asm volatile("mma.sync.aligned.m16n8k16.row.col.f32.bf16.bf16.f32 " \
        "{%0,%1,%2,%3}, {%4,%5,%6,%7}, {%8,%9}, {%0,%1,%2,%3};" \
        : "+f"((d)[0]), "+f"((d)[1]), "+f"((d)[2]), "+f"((d)[3]) \
        : "r"((a)[0]), "r"((a)[1]), "r"((a)[2]), "r"((a)[3]), "r"(b0), "r"(b1))

// ================= embedding =================
__global__ void embed_kernel(const int* __restrict__ tok,
                             const float* __restrict__ we,
                             const float* __restrict__ pt,
                             float* __restrict__ x,
                             bf16* __restrict__ xh, bf16* __restrict__ xl)
{
    int m = blockIdx.x;
    int t = tok[m];
    const float* wr = we + (size_t)t * DD;
    const float* pr = pt + (size_t)t * DD;
    size_t base = (size_t)m * DD;
    for (int j = threadIdx.x; j < DD; j += blockDim.x) {
        float v = wr[j] + pr[j];
        x[base + j] = v;
        bf16 h, l; split_bf16(v, h, l);
        xh[base + j] = h; xl[base + j] = l;
    }
}

// ========== weight transpose + bf16 split: W[K,N] -> Th/Tl [N,K] ======
__global__ __launch_bounds__(256)
void wsplit_kernel(const float* __restrict__ W, bf16* __restrict__ Th,
                   bf16* __restrict__ Tl, int K, int N)
{
    __shared__ float s[32][33];
    const float* Wb = W;
    bf16* Thb = Th;
    bf16* Tlb = Tl;
    int nb = blockIdx.x * 32, kb = blockIdx.y * 32;
    int tx = threadIdx.x & 31, ty = threadIdx.x >> 5;
    #pragma unroll
    for (int j = 0; j < 4; j++)
        s[ty + 8*j][tx] = Wb[(size_t)(kb + ty + 8*j) * N + nb + tx];
    __syncthreads();
    #pragma unroll
    for (int j = 0; j < 4; j++) {
        float v = s[tx][ty + 8*j];
        bf16 h, l; split_bf16(v, h, l);
        size_t o = (size_t)(nb + ty + 8*j) * K + kb + tx;
        Thb[o] = h; Tlb[o] = l;
    }
}

__global__ void bcat_kernel(const float* __restrict__ a, const float* __restrict__ b,
                            const float* __restrict__ c, float* __restrict__ dst, int n)
{
    int i = blockIdx.x * blockDim.x + threadIdx.x;
    if (i < n) { dst[i] = a[i]; dst[n + i] = b[i]; dst[2*n + i] = c[i]; }
}

// ================= bf16x3 mma.sync GEMM =================
// Tile 128x128, BK=32, 3-stage cp.async pipeline, 2 CTAs/SM.
// mode 0: fp32+bias; 1: relu->bf16 h/l; 2: +bias+Res->fp32; 3: QKV remap.
#define STAGE_B 32768                  // Ah(8K) Al(8K) Bh(8K) Bl(8K)
#define GSMEM (3*STAGE_B)              // 98304

__global__ __launch_bounds__(256, 2)
void gemm_kernel(const bf16* __restrict__ Ah, const bf16* __restrict__ Al,
                 const bf16* __restrict__ Bh_, const bf16* __restrict__ Bl_,
                 const float* __restrict__ bias_, const float* __restrict__ Res,
                 float* __restrict__ C_, bf16* __restrict__ Ch, bf16* __restrict__ Cl,
                 int K, int N, int mode, size_t zsB, size_t zsBias, size_t zsC)
{
    extern __shared__ char smem[];
    const uint32_t sb = smem_u32(smem);
    const int tid = threadIdx.x;
    const int lane = tid & 31, wid = tid >> 5;
    const int warp_m = wid & 3, warp_n = wid >> 2;
    const int m0 = blockIdx.y * 128, n0 = blockIdx.x * 128;

    const bf16* Bh = Bh_ + blockIdx.z * zsB;
    const bf16* Bl = Bl_ + blockIdx.z * zsB;
    const float* bias = bias_ + blockIdx.z * zsBias;
    float* C = C_ + blockIdx.z * zsC;

    int lrow0 = tid >> 2, lkg0 = tid & 3;
    int lrow1 = (tid + 256) >> 2;
    uint32_t soff0 = (uint32_t)(lrow0 * 64 + ((lkg0 ^ ((lrow0 >> 1) & 3)) << 4));
    uint32_t soff1 = (uint32_t)(lrow1 * 64 + ((lkg0 ^ ((lrow1 >> 1) & 3)) << 4));

    const bf16* gAh = Ah + (size_t)(m0 + lrow0) * K + lkg0 * 8;
    const bf16* gAl = Al + (size_t)(m0 + lrow0) * K + lkg0 * 8;
    const bf16* gBh = Bh + (size_t)(n0 + lrow0) * K + lkg0 * 8;
    const bf16* gBl = Bl + (size_t)(n0 + lrow0) * K + lkg0 * 8;
    const bf16* gAh1 = Ah + (size_t)(m0 + lrow1) * K + lkg0 * 8;
    const bf16* gAl1 = Al + (size_t)(m0 + lrow1) * K + lkg0 * 8;
    const bf16* gBh1 = Bh + (size_t)(n0 + lrow1) * K + lkg0 * 8;
    const bf16* gBl1 = Bl + (size_t)(n0 + lrow1) * K + lkg0 * 8;

    int matA = lane >> 3;
    int arow_local = ((matA & 1) << 3) + (lane & 7);
    int akgbit = matA >> 1;
    uint32_t offA[2][2];
    #pragma unroll
    for (int mt = 0; mt < 2; mt++) {
        int row = warp_m * 32 + mt * 16 + arow_local;
        int swz = (row >> 1) & 3;
        #pragma unroll
        for (int ks = 0; ks < 2; ks++)
            offA[mt][ks] = (uint32_t)(row * 64 + (((ks * 2 + akgbit) ^ swz) << 4));
    }
    int brow_local = ((matA >> 1) << 3) + (lane & 7);
    int bkgbit = lane >> 3 & 1;
    uint32_t offB[4][2];
    #pragma unroll
    for (int np = 0; np < 4; np++) {
        int row = warp_n * 64 + np * 16 + brow_local;
        int swz = (row >> 1) & 3;
        #pragma unroll
        for (int ks = 0; ks < 2; ks++)
            offB[np][ks] = (uint32_t)(row * 64 + (((ks * 2 + bkgbit) ^ swz) << 4));
    }

    float acc[2][8][4];
    #pragma unroll
    for (int i = 0; i < 2; i++)
        #pragma unroll
        for (int j = 0; j < 8; j++)
            #pragma unroll
            for (int qq = 0; qq < 4; qq++) acc[i][j][qq] = 0.f;

    const int NC = K >> 5;

    auto load_stage = [&](int stage, int chunk) {
        uint32_t base = sb + stage * STAGE_B;
        size_t gk = (size_t)(chunk << 5);
        CP_ASYNC16(base           + soff0, gAh  + gk);
        CP_ASYNC16(base +  8192u  + soff0, gAl  + gk);
        CP_ASYNC16(base + 16384u  + soff0, gBh  + gk);
        CP_ASYNC16(base + 24576u  + soff0, gBl  + gk);
        CP_ASYNC16(base           + soff1, gAh1 + gk);
        CP_ASYNC16(base +  8192u  + soff1, gAl1 + gk);
        CP_ASYNC16(base + 16384u  + soff1, gBh1 + gk);
        CP_ASYNC16(base + 24576u  + soff1, gBl1 + gk);
    };

    load_stage(0, 0); CP_COMMIT();
    if (NC > 1) load_stage(1, 1);
    CP_COMMIT();

    int cur = 0;
    for (int i = 0; i < NC; i++) {
        CP_WAIT1();
        __syncthreads();

        uint32_t base = sb + cur * STAGE_B;
        uint32_t sAh = base, sAl = base + 8192u, sBh = base + 16384u, sBl = base + 24576u;

        #pragma unroll
        for (int ks = 0; ks < 2; ks++) {
            uint32_t ah[2][4], al[2][4];
            #pragma unroll
            for (int mt = 0; mt < 2; mt++) {
                LDSM_X4(ah[mt][0], ah[mt][1], ah[mt][2], ah[mt][3], sAh + offA[mt][ks]);
                LDSM_X4(al[mt][0], al[mt][1], al[mt][2], al[mt][3], sAl + offA[mt][ks]);
            }
            #pragma unroll
            for (int np = 0; np < 4; np++) {
                uint32_t bh[4], bl[4];
                LDSM_X4(bh[0], bh[1], bh[2], bh[3], sBh + offB[np][ks]);
                LDSM_X4(bl[0], bl[1], bl[2], bl[3], sBl + offB[np][ks]);
                #pragma unroll
                for (int mt = 0; mt < 2; mt++) {
                    MMA_BF16(acc[mt][np*2+0], ah[mt], bh[0], bh[1]);
                    MMA_BF16(acc[mt][np*2+0], al[mt], bh[0], bh[1]);
                    MMA_BF16(acc[mt][np*2+0], ah[mt], bl[0], bl[1]);
                    MMA_BF16(acc[mt][np*2+1], ah[mt], bh[2], bh[3]);
                    MMA_BF16(acc[mt][np*2+1], al[mt], bh[2], bh[3]);
                    MMA_BF16(acc[mt][np*2+1], ah[mt], bl[2], bl[3]);
                }
            }
        }
        __syncthreads();
        if (i + 2 < NC) {
            int pf = cur + 2; if (pf >= 3) pf -= 3;
            load_stage(pf, i + 2);
        }
        CP_COMMIT();
        cur = (cur + 1 == 3) ? 0 : cur + 1;
    }

    // -------- epilogue --------
    #pragma unroll
    for (int mt = 0; mt < 2; mt++) {
        int r0 = m0 + warp_m * 32 + mt * 16 + (lane >> 2);
        int r1 = r0 + 8;
        #pragma unroll
        for (int nt = 0; nt < 8; nt++) {
            int c = n0 + warp_n * 64 + nt * 8 + ((lane & 3) << 1);
            float2 bv = *(const float2*)(bias + c);
            float v00 = acc[mt][nt][0] + bv.x, v01 = acc[mt][nt][1] + bv.y;
            float v10 = acc[mt][nt][2] + bv.x, v11 = acc[mt][nt][3] + bv.y;
            if (mode == 0) {
                *(float2*)(C + (size_t)r0 * N + c) = make_float2(v00, v01);
                *(float2*)(C + (size_t)r1 * N + c) = make_float2(v10, v11);
            } else if (mode == 1) {
                v00 = fmaxf(v00, 0.f); v01 = fmaxf(v01, 0.f);
                v10 = fmaxf(v10, 0.f); v11 = fmaxf(v11, 0.f);
                bf16 h0,l0,h1,l1,h2,l2,h3,l3;
                split_bf16(v00,h0,l0); split_bf16(v01,h1,l1);
                split_bf16(v10,h2,l2); split_bf16(v11,h3,l3);
                __nv_bfloat162 ph0; ph0.x = h0; ph0.y = h1;
                __nv_bfloat162 pl0; pl0.x = l0; pl0.y = l1;
                __nv_bfloat162 ph1; ph1.x = h2; ph1.y = h3;
                __nv_bfloat162 pl1; pl1.x = l2; pl1.y = l3;
                *(__nv_bfloat162*)(Ch + (size_t)r0 * N + c) = ph0;
                *(__nv_bfloat162*)(Cl + (size_t)r0 * N + c) = pl0;
                *(__nv_bfloat162*)(Ch + (size_t)r1 * N + c) = ph1;
                *(__nv_bfloat162*)(Cl + (size_t)r1 * N + c) = pl1;
            } else if (mode == 2) {
                float2 q0 = *(const float2*)(Res + (size_t)r0 * N + c);
                float2 q1 = *(const float2*)(Res + (size_t)r1 * N + c);
                *(float2*)(C + (size_t)r0 * N + c) = make_float2(v00 + q0.x, v01 + q0.y);
                *(float2*)(C + (size_t)r1 * N + c) = make_float2(v10 + q1.x, v11 + q1.y);
            } else {
                int b0_ = r0 >> 9, s0_ = r0 & 511;
                int b1_ = r1 >> 9, s1_ = r1 & 511;
                int h_ = c >> 6, d_ = c & 63;
                *(float2*)(C + ((((size_t)b0_ * HH + h_) * SS + s0_) << 6) + d_) = make_float2(v00, v01);
                *(float2*)(C + ((((size_t)b1_ * HH + h_) * SS + s1_) << 6) + d_) = make_float2(v10, v11);
            }
        }
    }
}

// ================= fused attention: 32 queries/block, cp.async double-buffered =================
// smem floats: qsT[64][36] | sc[32][513] | kv[2][64][68]
#define A_QST 0
#define A_SC  (64*36)
#define A_KV  (64*36 + 32*513)
#define KVSZ  (64*68)
#define A_TOT (64*36 + 32*513 + 2*KVSZ)   // 27424 floats = 109696 B

__global__ __launch_bounds__(256, 2)
void attn_kernel(const float* __restrict__ q, const float* __restrict__ k,
                 const float* __restrict__ v, const int* __restrict__ tok,
                 float* __restrict__ probs, bf16* __restrict__ avh, bf16* __restrict__ avl)
{
    extern __shared__ float sm[];
    float* qsT = sm + A_QST;
    float* sc  = sm + A_SC;
    float* kv  = sm + A_KV;
    int qb = blockIdx.x, h = blockIdx.y, b = blockIdx.z;
    int tid = threadIdx.x;

    const float* qbase = q + ((((size_t)b * HH + h) * SS + qb * 32) << 6);
    #pragma unroll
    for (int t = 0; t < 2; t++) {
        int j = tid + 256 * t;            // 512 float4 groups
        int row = j >> 4, c4 = j & 15;
        float4 qv = *(const float4*)(qbase + row * 64 + c4 * 4);
        qsT[(c4*4+0)*36 + row] = qv.x;
        qsT[(c4*4+1)*36 + row] = qv.y;
        qsT[(c4*4+2)*36 + row] = qv.z;
        qsT[(c4*4+3)*36 + row] = qv.w;
    }

    const float* kbase = k + (((size_t)b * HH + h) * SS << 6);
    const float* vbase = v + (((size_t)b * HH + h) * SS << 6);
    const int* tb = tok + b * SS;
    const int qgrp = tid & 7, kgrp = tid >> 3;

    // async prefetch of a 64x64 chunk into kv buffer buf (0/1)
    auto pf = [&](const float* gsrc, int buf) {
        uint32_t sdst = smem_u32(kv + buf * KVSZ);
        #pragma unroll
        for (int t = 0; t < 4; t++) {
            int j = tid + 256 * t;
            int row = j >> 4, c4 = j & 15;
            CP_ASYNC16(sdst + (uint32_t)(row * 68 + c4 * 4) * 4,
                       gsrc + (size_t)row * 64 + c4 * 4);
        }
    };

    pf(kbase, 0); CP_COMMIT();
    __syncthreads();   // qsT visible

    // ---- scores: 8 chunks of 64 keys, double-buffered ----
    for (int ch = 0; ch < 8; ch++) {
        if (ch < 7) pf(kbase + (size_t)(ch + 1) * 64 * 64, (ch + 1) & 1);
        CP_COMMIT();
        CP_WAIT1();
        __syncthreads();
        const float* kvb = kv + (ch & 1) * KVSZ;
        float acc[4][2] = {};
        #pragma unroll
        for (int d = 0; d < 64; d++) {
            float4 qv = *(const float4*)(qsT + d * 36 + qgrp * 4);
            float k0 = kvb[(kgrp*2+0)*68 + d];
            float k1 = kvb[(kgrp*2+1)*68 + d];
            acc[0][0] = fmaf(qv.x, k0, acc[0][0]); acc[0][1] = fmaf(qv.x, k1, acc[0][1]);
            acc[1][0] = fmaf(qv.y, k0, acc[1][0]); acc[1][1] = fmaf(qv.y, k1, acc[1][1]);
            acc[2][0] = fmaf(qv.z, k0, acc[2][0]); acc[2][1] = fmaf(qv.z, k1, acc[2][1]);
            acc[3][0] = fmaf(qv.w, k0, acc[3][0]); acc[3][1] = fmaf(qv.w, k1, acc[3][1]);
        }
        #pragma unroll
        for (int j = 0; j < 2; j++) {
            int key = ch * 64 + kgrp * 2 + j;
            bool msk = (tb[key] == 0);
            #pragma unroll
            for (int i = 0; i < 4; i++)
                sc[(qgrp*4+i)*513 + key] = msk ? -INFINITY : acc[i][j] * 0.125f;
        }
        __syncthreads();
    }

    // prefetch V chunk 0 before softmax (fully hidden)
    pf(vbase, 0); CP_COMMIT();

    // ---- softmax: 8 warps x 4 rows ----
    int w = tid >> 5, lane = tid & 31;
    #pragma unroll 1
    for (int rr = 0; rr < 4; rr++) {
        int row = w * 4 + rr;
        float* srow = sc + row * 513;
        float m = -INFINITY;
        for (int j = lane; j < 512; j += 32) m = fmaxf(m, srow[j]);
        #pragma unroll
        for (int o = 16; o > 0; o >>= 1) m = fmaxf(m, __shfl_xor_sync(~0u, m, o));
        float sum = 0.f;
        for (int j = lane; j < 512; j += 32) {
            float e = __expf(srow[j] - m);
            srow[j] = e; sum += e;
        }
        #pragma unroll
        for (int o = 16; o > 0; o >>= 1) sum += __shfl_xor_sync(~0u, sum, o);
        float inv = 1.f / sum;
        float* prow = probs + ((((size_t)b * HH + h) * SS + qb * 32 + row) << 9);
        for (int j = lane; j < 512; j += 32) {
            float p = srow[j] * inv;
            srow[j] = p;
            prow[j] = p;
        }
    }
    __syncthreads();

    // ---- AV: double-buffered V chunks ----
    int ql = tid & 31, dg = tid >> 5;
    float a8[8] = {};
    for (int ch = 0; ch < 8; ch++) {
        if (ch < 7) pf(vbase + (size_t)(ch + 1) * 64 * 64, (ch + 1) & 1);
        CP_COMMIT();
        CP_WAIT1();
        __syncthreads();
        const float* kvb = kv + (ch & 1) * KVSZ;
        const float* srow = sc + ql * 513 + ch * 64;
        #pragma unroll 4
        for (int kk = 0; kk < 64; kk++) {
            float s = srow[kk];
            float4 v0 = *(const float4*)(kvb + kk * 68 + dg * 8);
            float4 v1 = *(const float4*)(kvb + kk * 68 + dg * 8 + 4);
            a8[0] = fmaf(s, v0.x, a8[0]); a8[1] = fmaf(s, v0.y, a8[1]);
            a8[2] = fmaf(s, v0.z, a8[2]); a8[3] = fmaf(s, v0.w, a8[3]);
            a8[4] = fmaf(s, v1.x, a8[4]); a8[5] = fmaf(s, v1.y, a8[5]);
            a8[6] = fmaf(s, v1.z, a8[6]); a8[7] = fmaf(s, v1.w, a8[7]);
        }
        __syncthreads();
    }
    size_t o = ((size_t)(b * SS + qb * 32 + ql) << 10) + h * 64 + dg * 8;
    uint32_t ph[4], pl[4];
    #pragma unroll
    for (int i = 0; i < 4; i++) {
        bf16 h0, l0, h1, l1;
        split_bf16(a8[2*i], h0, l0);
        split_bf16(a8[2*i+1], h1, l1);
        ph[i] = ((uint32_t)__bfloat16_as_ushort(h1) << 16) | __bfloat16_as_ushort(h0);
        pl[i] = ((uint32_t)__bfloat16_as_ushort(l1) << 16) | __bfloat16_as_ushort(l0);
    }
    *(uint4*)(avh + o) = make_uint4(ph[0], ph[1], ph[2], ph[3]);
    *(uint4*)(avl + o) = make_uint4(pl[0], pl[1], pl[2], pl[3]);
}

// ================= layernorm + bf16 split =================
__global__ __launch_bounds__(256)
void ln_kernel(const float* __restrict__ in, float* __restrict__ out,
               bf16* __restrict__ oh, bf16* __restrict__ ol)
{
    int row = blockIdx.x;
    int tid = threadIdx.x;
    const float* r = in + (size_t)row * DD;
    float v0 = r[tid], v1 = r[tid + 256], v2 = r[tid + 512], v3 = r[tid + 768];
    float s = v0 + v1 + v2 + v3;

    __shared__ float sh[32];
    #pragma unroll
    for (int o = 16; o > 0; o >>= 1) s += __shfl_down_sync(~0u, s, o);
    if ((tid & 31) == 0) sh[tid >> 5] = s;
    __syncthreads();
    if (tid < 8) {
        s = sh[tid];
        #pragma unroll
        for (int o = 4; o > 0; o >>= 1) s += __shfl_down_sync(0xffu, s, o);
        if (tid == 0) sh[0] = s;
    }
    __syncthreads();
    float mean = sh[0] * (1.f / 1024.f);
    float d0 = v0 - mean, d1 = v1 - mean, d2 = v2 - mean, d3 = v3 - mean;
    float qv = d0*d0 + d1*d1 + d2*d2 + d3*d3;
    __syncthreads();
    #pragma unroll
    for (int o = 16; o > 0; o >>= 1) qv += __shfl_down_sync(~0u, qv, o);
    if ((tid & 31) == 0) sh[tid >> 5] = qv;
    __syncthreads();
    if (tid < 8) {
        qv = sh[tid];
        #pragma unroll
        for (int o = 4; o > 0; o >>= 1) qv += __shfl_down_sync(0xffu, qv, o);
        if (tid == 0) sh[0] = qv;
    }
    __syncthreads();
    float inv = rsqrtf(sh[0] * (1.f / 1024.f) + 1e-5f);
    size_t base = (size_t)row * DD;
    #pragma unroll
    for (int jj = 0; jj < 4; jj++) {
        float d = (jj == 0 ? d0 : jj == 1 ? d1 : jj == 2 ? d2 : d3);
        float val = d * inv;
        int idx = tid + jj * 256;
        out[base + idx] = val;
        bf16 h, l; split_bf16(val, h, l);
        oh[base + idx] = h; ol[base + idx] = l;
    }
}

// ================= host driver =================
extern "C" void kernel_launch(void* const* d_in, const int* in_sizes, int n_in,
                              void* d_out, int out_size)
{
    const int*   tok = (const int*)d_in[0];
    const float* we  = (const float*)d_in[1];
    const float* pt  = (const float*)d_in[2];
    const float* Wq  = (const float*)d_in[3];  const float* bq = (const float*)d_in[4];
    const float* Wk  = (const float*)d_in[5];  const float* bk = (const float*)d_in[6];
    const float* Wv  = (const float*)d_in[7];  const float* bv = (const float*)d_in[8];
    const float* Wo  = (const float*)d_in[9];  const float* bo = (const float*)d_in[10];
    const float* W1  = (const float*)d_in[11]; const float* b1 = (const float*)d_in[12];
    const float* W2  = (const float*)d_in[13]; const float* b2 = (const float*)d_in[14];
    float* out = (float*)d_out;

    float *x, *qkv, *yp, *x1p, *bqkv;
    bf16 *xh, *xl, *avh, *avl, *x1h, *x1l, *ffh, *ffl;
    cudaGetSymbolAddress((void**)&x,   g_x);
    cudaGetSymbolAddress((void**)&xh,  g_xh);  cudaGetSymbolAddress((void**)&xl,  g_xl);
    cudaGetSymbolAddress((void**)&qkv, g_qkv);
    cudaGetSymbolAddress((void**)&avh, g_avh); cudaGetSymbolAddress((void**)&avl, g_avl);
    cudaGetSymbolAddress((void**)&yp,  g_y);
    cudaGetSymbolAddress((void**)&x1p, g_x1);
    cudaGetSymbolAddress((void**)&x1h, g_x1h); cudaGetSymbolAddress((void**)&x1l, g_x1l);
    cudaGetSymbolAddress((void**)&ffh, g_ffh); cudaGetSymbolAddress((void**)&ffl, g_ffl);
    cudaGetSymbolAddress((void**)&bqkv, g_bqkv);

    bf16 *wqkvh, *wqkvl, *woh, *wol, *w1h, *w1l, *w2h, *w2l;
    cudaGetSymbolAddress((void**)&wqkvh, g_wqkvT_h); cudaGetSymbolAddress((void**)&wqkvl, g_wqkvT_l);
    cudaGetSymbolAddress((void**)&woh, g_woT_h); cudaGetSymbolAddress((void**)&wol, g_woT_l);
    cudaGetSymbolAddress((void**)&w1h, g_w1T_h); cudaGetSymbolAddress((void**)&w1l, g_w1T_l);
    cudaGetSymbolAddress((void**)&w2h, g_w2T_h); cudaGetSymbolAddress((void**)&w2l, g_w2T_l);

    cudaFuncSetAttribute(gemm_kernel, cudaFuncAttributeMaxDynamicSharedMemorySize, GSMEM);
    cudaFuncSetAttribute(attn_kernel, cudaFuncAttributeMaxDynamicSharedMemorySize, A_TOT * 4);

    // side stream + events for overlapped weight preprocessing (created once; host-side only)
    static cudaStream_t s2 = nullptr;
    static cudaEvent_t eFork = nullptr, eLay[LL];
    if (!s2) {
        cudaStreamCreate(&s2);
        cudaEventCreateWithFlags(&eFork, cudaEventDisableTiming);
        for (int l = 0; l < LL; l++) cudaEventCreateWithFlags(&eLay[l], cudaEventDisableTiming);
    }

    const size_t PROJ = (size_t)DD * DD;
    const size_t WQKV = (size_t)LL * DD * DD;
    const size_t W1SZ = (size_t)DD * DFF;
    const size_t W2SZ = (size_t)DFF * DD;
    const size_t CORR = (size_t)BB * HH * SS * SS;
    const size_t QKVS = (size_t)MTOK * DD;

    // per-layer weight split enqueue
    auto split_layer = [&](int l, cudaStream_t st) {
        dim3 gP(DD/32, DD/32);
        wsplit_kernel<<<gP, 256, 0, st>>>(Wq + l*PROJ, wqkvh + l*PROJ,          wqkvl + l*PROJ,          DD, DD);
        wsplit_kernel<<<gP, 256, 0, st>>>(Wk + l*PROJ, wqkvh + WQKV + l*PROJ,   wqkvl + WQKV + l*PROJ,   DD, DD);
        wsplit_kernel<<<gP, 256, 0, st>>>(Wv + l*PROJ, wqkvh + 2*WQKV + l*PROJ, wqkvl + 2*WQKV + l*PROJ, DD, DD);
        wsplit_kernel<<<gP, 256, 0, st>>>(Wo + l*PROJ, woh + l*PROJ, wol + l*PROJ, DD, DD);
        dim3 g1(DFF/32, DD/32);
        wsplit_kernel<<<g1, 256, 0, st>>>(W1 + l*W1SZ, w1h + l*W1SZ, w1l + l*W1SZ, DD, DFF);
        dim3 g2(DD/32, DFF/32);
        wsplit_kernel<<<g2, 256, 0, st>>>(W2 + l*W2SZ, w2h + l*W2SZ, w2l + l*W2SZ, DFF, DD);
    };

    // layer-0 weights + biases + embedding on the main stream
    bcat_kernel<<<(LL*DD + 255)/256, 256>>>(bq, bk, bv, bqkv, LL*DD);
    split_layer(0, (cudaStream_t)0);
    embed_kernel<<<MTOK, 256>>>(tok, we, pt, x, xh, xl);

    // fork: layers 1..5 weight splits on s2, overlapped with compute
    cudaEventRecord(eFork, (cudaStream_t)0);
    cudaStreamWaitEvent(s2, eFork, 0);
    for (int l = 1; l < LL; l++) {
        split_layer(l, s2);
        cudaEventRecord(eLay[l], s2);
    }

    dim3 gQKV(DD / 128, MTOK / 128, 3);   // (8,16,3)
    dim3 gD  (DD / 128, MTOK / 128);      // (8,16)
    dim3 gFF (DFF / 128, MTOK / 128);     // (32,16)
    dim3 gA  (SS / 32, HH, BB);           // (16,16,4)

    float* qp = qkv;
    float* kp = qkv + QKVS;
    float* vp = qkv + 2*QKVS;

    for (int l = 0; l < LL; l++) {
        if (l > 0) cudaStreamWaitEvent((cudaStream_t)0, eLay[l], 0);

        gemm_kernel<<<gQKV, 256, GSMEM>>>(xh, xl, wqkvh + l*PROJ, wqkvl + l*PROJ,
                                          bqkv + l*DD, nullptr, qkv, nullptr, nullptr,
                                          DD, DD, 3, WQKV, (size_t)LL*DD, QKVS);

        float* probs_l = out + (size_t)MTOK * DD + (size_t)l * CORR;
        attn_kernel<<<gA, 256, A_TOT*4>>>(qp, kp, vp, tok, probs_l, avh, avl);

        gemm_kernel<<<gD, 256, GSMEM>>>(avh, avl, woh + l*PROJ, wol + l*PROJ, bo + l*DD,
                                        x, yp, nullptr, nullptr, DD, DD, 2, 0, 0, 0);
        ln_kernel<<<MTOK, 256>>>(yp, x1p, x1h, x1l);

        gemm_kernel<<<gFF, 256, GSMEM>>>(x1h, x1l, w1h + l*W1SZ, w1l + l*W1SZ, b1 + l*DFF,
                                         nullptr, nullptr, ffh, ffl, DD, DFF, 1, 0, 0, 0);
        gemm_kernel<<<gD, 256, GSMEM>>>(ffh, ffl, w2h + l*W2SZ, w2l + l*W2SZ, b2 + l*DD,
                                        x1p, yp, nullptr, nullptr, DFF, DD, 2, 0, 0, 0);

        // final layer writes hidden states straight into out
        float* xdst = (l == LL - 1) ? out : x;
        ln_kernel<<<MTOK, 256>>>(yp, xdst, xh, xl);
    }
}

// round 6
// speedup vs baseline: 1.2883x; 1.2883x over previous
#include <cuda_runtime.h>
#include <cuda_fp16.h>
#include <math.h>
#include <stdint.h>

// Problem constants
#define BB 4
#define SS 512
#define DD 1024
#define HH 16
#define DHH 64
#define DFF 4096
#define LL 6
#define MTOK (BB*SS)          // 2048 token rows

typedef __half fp16;

// ================= device scratch =================
__device__ float g_x  [MTOK*DD];    // residual stream fp32
__device__ fp16  g_xh [MTOK*DD],  g_xl [MTOK*DD];
__device__ float g_qkv[3*MTOK*DD];  // Q,K,V in [3][B,H,S,64]
__device__ fp16  g_avh[MTOK*DD],  g_avl[MTOK*DD];
__device__ float g_y  [MTOK*DD];
__device__ float g_x1 [MTOK*DD];
__device__ fp16  g_x1h[MTOK*DD],  g_x1l[MTOK*DD];
__device__ fp16  g_ffh[MTOK*DFF], g_ffl[MTOK*DFF];

// transposed fp16 weights: [N, K] K-major per layer (high part only; A carries the precision)
__device__ fp16 g_wqkvT[3*LL*DD*DD];   // [3][L][N][K]
__device__ fp16 g_woT[LL*DD*DD];
__device__ fp16 g_w1T[LL*DD*DFF];
__device__ fp16 g_w2T[LL*DFF*DD];
__device__ float g_bqkv[3*LL*DD];

// ================= small helpers =================
__device__ __forceinline__ uint32_t smem_u32(const void* p) {
    uint32_t a;
    asm("{ .reg .u64 t; cvta.to.shared.u64 t, %1; cvt.u32.u64 %0, t; }" : "=r"(a) : "l"(p));
    return a;
}
__device__ __forceinline__ void split_fp16(float v, fp16& h, fp16& l) {
    h = __float2half_rn(v);
    l = __float2half_rn(v - __half2float(h));
}

#define CP_ASYNC16(sa, ga) \
    asm volatile("cp.async.cg.shared.global [%0], [%1], 16;" :: "r"(sa), "l"(ga) : "memory")
#define CP_COMMIT() asm volatile("cp.async.commit_group;" ::: "memory")
#define CP_WAIT1()  asm volatile("cp.async.wait_group 1;" ::: "memory")

#define LDSM_X4(r0,r1,r2,r3, addr) \
    asm volatile("ldmatrix.sync.aligned.m8n8.x4.shared.b16 {%0,%1,%2,%3}, [%4];" \
        : "=r"(r0), "=r"(r1), "=r"(r2), "=r"(r3) : "r"(addr))

#define MMA_F16(d, a, b0, b1) \
    asm volatile("mma.sync.aligned.m16n8k16.row.col.f32.f16.f16.f32 " \
        "{%0,%1,%2,%3}, {%4,%5,%6,%7}, {%8,%9}, {%0,%1,%2,%3};" \
        : "+f"((d)[0]), "+f"((d)[1]), "+f"((d)[2]), "+f"((d)[3]) \
        : "r"((a)[0]), "r"((a)[1]), "r"((a)[2]), "r"((a)[3]), "r"(b0), "r"(b1))

// ================= embedding =================
__global__ void embed_kernel(const int* __restrict__ tok,
                             const float* __restrict__ we,
                             const float* __restrict__ pt,
                             float* __restrict__ x,
                             fp16* __restrict__ xh, fp16* __restrict__ xl)
{
    int m = blockIdx.x;
    int t = tok[m];
    const float* wr = we + (size_t)t * DD;
    const float* pr = pt + (size_t)t * DD;
    size_t base = (size_t)m * DD;
    for (int j = threadIdx.x; j < DD; j += blockDim.x) {
        float v = wr[j] + pr[j];
        x[base + j] = v;
        fp16 h, l; split_fp16(v, h, l);
        xh[base + j] = h; xl[base + j] = l;
    }
}

// ========== weight transpose + fp16 round: W[K,N] -> T [N,K] ======
__global__ __launch_bounds__(256)
void wsplit_kernel(const float* __restrict__ W, fp16* __restrict__ Th, int K, int N)
{
    __shared__ float s[32][33];
    int nb = blockIdx.x * 32, kb = blockIdx.y * 32;
    int tx = threadIdx.x & 31, ty = threadIdx.x >> 5;
    #pragma unroll
    for (int j = 0; j < 4; j++)
        s[ty + 8*j][tx] = W[(size_t)(kb + ty + 8*j) * N + nb + tx];
    __syncthreads();
    #pragma unroll
    for (int j = 0; j < 4; j++) {
        float v = s[tx][ty + 8*j];
        Th[(size_t)(nb + ty + 8*j) * K + kb + tx] = __float2half_rn(v);
    }
}

__global__ void bcat_kernel(const float* __restrict__ a, const float* __restrict__ b,
                            const float* __restrict__ c, float* __restrict__ dst, int n)
{
    int i = blockIdx.x * blockDim.x + threadIdx.x;
    if (i < n) { dst[i] = a[i]; dst[n + i] = b[i]; dst[2*n + i] = c[i]; }
}

// ================= fp16x2 mma.sync GEMM: D = Ah*B + Al*B =================
// Tile 128x128, BK=32, 3-stage cp.async pipeline, 2 CTAs/SM.
// mode 0: fp32+bias; 1: relu->fp16 h/l; 2: +bias+Res->fp32; 3: QKV remap.
#define STAGE_B 24576                  // Ah(8K) Al(8K) Bh(8K)
#define GSMEM (3*STAGE_B)              // 73728

__global__ __launch_bounds__(256, 2)
void gemm_kernel(const fp16* __restrict__ Ah, const fp16* __restrict__ Al,
                 const fp16* __restrict__ Bh_,
                 const float* __restrict__ bias_, const float* __restrict__ Res,
                 float* __restrict__ C_, fp16* __restrict__ Ch, fp16* __restrict__ Cl,
                 int K, int N, int mode, size_t zsB, size_t zsBias, size_t zsC)
{
    extern __shared__ char smem[];
    const uint32_t sb = smem_u32(smem);
    const int tid = threadIdx.x;
    const int lane = tid & 31, wid = tid >> 5;
    const int warp_m = wid & 3, warp_n = wid >> 2;
    const int m0 = blockIdx.y * 128, n0 = blockIdx.x * 128;

    const fp16* Bh = Bh_ + blockIdx.z * zsB;
    const float* bias = bias_ + blockIdx.z * zsBias;
    float* C = C_ + blockIdx.z * zsC;

    int lrow0 = tid >> 2, lkg0 = tid & 3;
    int lrow1 = (tid + 256) >> 2;
    uint32_t soff0 = (uint32_t)(lrow0 * 64 + ((lkg0 ^ ((lrow0 >> 1) & 3)) << 4));
    uint32_t soff1 = (uint32_t)(lrow1 * 64 + ((lkg0 ^ ((lrow1 >> 1) & 3)) << 4));

    const fp16* gAh = Ah + (size_t)(m0 + lrow0) * K + lkg0 * 8;
    const fp16* gAl = Al + (size_t)(m0 + lrow0) * K + lkg0 * 8;
    const fp16* gBh = Bh + (size_t)(n0 + lrow0) * K + lkg0 * 8;
    const fp16* gAh1 = Ah + (size_t)(m0 + lrow1) * K + lkg0 * 8;
    const fp16* gAl1 = Al + (size_t)(m0 + lrow1) * K + lkg0 * 8;
    const fp16* gBh1 = Bh + (size_t)(n0 + lrow1) * K + lkg0 * 8;

    int matA = lane >> 3;
    int arow_local = ((matA & 1) << 3) + (lane & 7);
    int akgbit = matA >> 1;
    uint32_t offA[2][2];
    #pragma unroll
    for (int mt = 0; mt < 2; mt++) {
        int row = warp_m * 32 + mt * 16 + arow_local;
        int swz = (row >> 1) & 3;
        #pragma unroll
        for (int ks = 0; ks < 2; ks++)
            offA[mt][ks] = (uint32_t)(row * 64 + (((ks * 2 + akgbit) ^ swz) << 4));
    }
    int brow_local = ((matA >> 1) << 3) + (lane & 7);
    int bkgbit = lane >> 3 & 1;
    uint32_t offB[4][2];
    #pragma unroll
    for (int np = 0; np < 4; np++) {
        int row = warp_n * 64 + np * 16 + brow_local;
        int swz = (row >> 1) & 3;
        #pragma unroll
        for (int ks = 0; ks < 2; ks++)
            offB[np][ks] = (uint32_t)(row * 64 + (((ks * 2 + bkgbit) ^ swz) << 4));
    }

    float acc[2][8][4];
    #pragma unroll
    for (int i = 0; i < 2; i++)
        #pragma unroll
        for (int j = 0; j < 8; j++)
            #pragma unroll
            for (int qq = 0; qq < 4; qq++) acc[i][j][qq] = 0.f;

    const int NC = K >> 5;

    auto load_stage = [&](int stage, int chunk) {
        uint32_t base = sb + stage * STAGE_B;
        size_t gk = (size_t)(chunk << 5);
        CP_ASYNC16(base           + soff0, gAh  + gk);
        CP_ASYNC16(base +  8192u  + soff0, gAl  + gk);
        CP_ASYNC16(base + 16384u  + soff0, gBh  + gk);
        CP_ASYNC16(base           + soff1, gAh1 + gk);
        CP_ASYNC16(base +  8192u  + soff1, gAl1 + gk);
        CP_ASYNC16(base + 16384u  + soff1, gBh1 + gk);
    };

    load_stage(0, 0); CP_COMMIT();
    if (NC > 1) load_stage(1, 1);
    CP_COMMIT();

    int cur = 0;
    for (int i = 0; i < NC; i++) {
        CP_WAIT1();
        __syncthreads();

        uint32_t base = sb + cur * STAGE_B;
        uint32_t sAh = base, sAl = base + 8192u, sBh = base + 16384u;

        #pragma unroll
        for (int ks = 0; ks < 2; ks++) {
            uint32_t ah[2][4], al[2][4];
            #pragma unroll
            for (int mt = 0; mt < 2; mt++) {
                LDSM_X4(ah[mt][0], ah[mt][1], ah[mt][2], ah[mt][3], sAh + offA[mt][ks]);
                LDSM_X4(al[mt][0], al[mt][1], al[mt][2], al[mt][3], sAl + offA[mt][ks]);
            }
            #pragma unroll
            for (int np = 0; np < 4; np++) {
                uint32_t bh[4];
                LDSM_X4(bh[0], bh[1], bh[2], bh[3], sBh + offB[np][ks]);
                #pragma unroll
                for (int mt = 0; mt < 2; mt++) {
                    MMA_F16(acc[mt][np*2+0], ah[mt], bh[0], bh[1]);
                    MMA_F16(acc[mt][np*2+0], al[mt], bh[0], bh[1]);
                    MMA_F16(acc[mt][np*2+1], ah[mt], bh[2], bh[3]);
                    MMA_F16(acc[mt][np*2+1], al[mt], bh[2], bh[3]);
                }
            }
        }
        __syncthreads();
        if (i + 2 < NC) {
            int pf = cur + 2; if (pf >= 3) pf -= 3;
            load_stage(pf, i + 2);
        }
        CP_COMMIT();
        cur = (cur + 1 == 3) ? 0 : cur + 1;
    }

    // -------- epilogue --------
    #pragma unroll
    for (int mt = 0; mt < 2; mt++) {
        int r0 = m0 + warp_m * 32 + mt * 16 + (lane >> 2);
        int r1 = r0 + 8;
        #pragma unroll
        for (int nt = 0; nt < 8; nt++) {
            int c = n0 + warp_n * 64 + nt * 8 + ((lane & 3) << 1);
            float2 bv = *(const float2*)(bias + c);
            float v00 = acc[mt][nt][0] + bv.x, v01 = acc[mt][nt][1] + bv.y;
            float v10 = acc[mt][nt][2] + bv.x, v11 = acc[mt][nt][3] + bv.y;
            if (mode == 0) {
                *(float2*)(C + (size_t)r0 * N + c) = make_float2(v00, v01);
                *(float2*)(C + (size_t)r1 * N + c) = make_float2(v10, v11);
            } else if (mode == 1) {
                v00 = fmaxf(v00, 0.f); v01 = fmaxf(v01, 0.f);
                v10 = fmaxf(v10, 0.f); v11 = fmaxf(v11, 0.f);
                fp16 h0,l0,h1,l1,h2,l2,h3,l3;
                split_fp16(v00,h0,l0); split_fp16(v01,h1,l1);
                split_fp16(v10,h2,l2); split_fp16(v11,h3,l3);
                __half2 ph0 = __halves2half2(h0, h1), pl0 = __halves2half2(l0, l1);
                __half2 ph1 = __halves2half2(h2, h3), pl1 = __halves2half2(l2, l3);
                *(__half2*)(Ch + (size_t)r0 * N + c) = ph0;
                *(__half2*)(Cl + (size_t)r0 * N + c) = pl0;
                *(__half2*)(Ch + (size_t)r1 * N + c) = ph1;
                *(__half2*)(Cl + (size_t)r1 * N + c) = pl1;
            } else if (mode == 2) {
                float2 q0 = *(const float2*)(Res + (size_t)r0 * N + c);
                float2 q1 = *(const float2*)(Res + (size_t)r1 * N + c);
                *(float2*)(C + (size_t)r0 * N + c) = make_float2(v00 + q0.x, v01 + q0.y);
                *(float2*)(C + (size_t)r1 * N + c) = make_float2(v10 + q1.x, v11 + q1.y);
            } else {
                int b0_ = r0 >> 9, s0_ = r0 & 511;
                int b1_ = r1 >> 9, s1_ = r1 & 511;
                int h_ = c >> 6, d_ = c & 63;
                *(float2*)(C + ((((size_t)b0_ * HH + h_) * SS + s0_) << 6) + d_) = make_float2(v00, v01);
                *(float2*)(C + ((((size_t)b1_ * HH + h_) * SS + s1_) << 6) + d_) = make_float2(v10, v11);
            }
        }
    }
}

// ================= fused attention: 32 queries/block, cp.async double-buffered =================
// smem floats: qsT[64][36] | sc[32][513] | kv[2][64][68]
#define A_QST 0
#define A_SC  (64*36)
#define A_KV  (64*36 + 32*513)
#define KVSZ  (64*68)
#define A_TOT (64*36 + 32*513 + 2*KVSZ)   // 27424 floats = 109696 B

__global__ __launch_bounds__(256, 2)
void attn_kernel(const float* __restrict__ q, const float* __restrict__ k,
                 const float* __restrict__ v, const int* __restrict__ tok,
                 float* __restrict__ probs, fp16* __restrict__ avh, fp16* __restrict__ avl)
{
    extern __shared__ float sm[];
    float* qsT = sm + A_QST;
    float* sc  = sm + A_SC;
    float* kv  = sm + A_KV;
    int qb = blockIdx.x, h = blockIdx.y, b = blockIdx.z;
    int tid = threadIdx.x;

    const float* qbase = q + ((((size_t)b * HH + h) * SS + qb * 32) << 6);
    #pragma unroll
    for (int t = 0; t < 2; t++) {
        int j = tid + 256 * t;
        int row = j >> 4, c4 = j & 15;
        float4 qv = *(const float4*)(qbase + row * 64 + c4 * 4);
        qsT[(c4*4+0)*36 + row] = qv.x;
        qsT[(c4*4+1)*36 + row] = qv.y;
        qsT[(c4*4+2)*36 + row] = qv.z;
        qsT[(c4*4+3)*36 + row] = qv.w;
    }

    const float* kbase = k + (((size_t)b * HH + h) * SS << 6);
    const float* vbase = v + (((size_t)b * HH + h) * SS << 6);
    const int* tb = tok + b * SS;
    const int qgrp = tid & 7, kgrp = tid >> 3;

    auto pf = [&](const float* gsrc, int buf) {
        uint32_t sdst = smem_u32(kv + buf * KVSZ);
        #pragma unroll
        for (int t = 0; t < 4; t++) {
            int j = tid + 256 * t;
            int row = j >> 4, c4 = j & 15;
            CP_ASYNC16(sdst + (uint32_t)(row * 68 + c4 * 4) * 4,
                       gsrc + (size_t)row * 64 + c4 * 4);
        }
    };

    pf(kbase, 0); CP_COMMIT();
    __syncthreads();

    for (int ch = 0; ch < 8; ch++) {
        if (ch < 7) pf(kbase + (size_t)(ch + 1) * 64 * 64, (ch + 1) & 1);
        CP_COMMIT();
        CP_WAIT1();
        __syncthreads();
        const float* kvb = kv + (ch & 1) * KVSZ;
        float acc[4][2] = {};
        #pragma unroll
        for (int d = 0; d < 64; d++) {
            float4 qv = *(const float4*)(qsT + d * 36 + qgrp * 4);
            float k0 = kvb[(kgrp*2+0)*68 + d];
            float k1 = kvb[(kgrp*2+1)*68 + d];
            acc[0][0] = fmaf(qv.x, k0, acc[0][0]); acc[0][1] = fmaf(qv.x, k1, acc[0][1]);
            acc[1][0] = fmaf(qv.y, k0, acc[1][0]); acc[1][1] = fmaf(qv.y, k1, acc[1][1]);
            acc[2][0] = fmaf(qv.z, k0, acc[2][0]); acc[2][1] = fmaf(qv.z, k1, acc[2][1]);
            acc[3][0] = fmaf(qv.w, k0, acc[3][0]); acc[3][1] = fmaf(qv.w, k1, acc[3][1]);
        }
        #pragma unroll
        for (int j = 0; j < 2; j++) {
            int key = ch * 64 + kgrp * 2 + j;
            bool msk = (tb[key] == 0);
            #pragma unroll
            for (int i = 0; i < 4; i++)
                sc[(qgrp*4+i)*513 + key] = msk ? -INFINITY : acc[i][j] * 0.125f;
        }
        __syncthreads();
    }

    pf(vbase, 0); CP_COMMIT();

    int w = tid >> 5, lane = tid & 31;
    #pragma unroll 1
    for (int rr = 0; rr < 4; rr++) {
        int row = w * 4 + rr;
        float* srow = sc + row * 513;
        float m = -INFINITY;
        for (int j = lane; j < 512; j += 32) m = fmaxf(m, srow[j]);
        #pragma unroll
        for (int o = 16; o > 0; o >>= 1) m = fmaxf(m, __shfl_xor_sync(~0u, m, o));
        float sum = 0.f;
        for (int j = lane; j < 512; j += 32) {
            float e = __expf(srow[j] - m);
            srow[j] = e; sum += e;
        }
        #pragma unroll
        for (int o = 16; o > 0; o >>= 1) sum += __shfl_xor_sync(~0u, sum, o);
        float inv = 1.f / sum;
        float* prow = probs + ((((size_t)b * HH + h) * SS + qb * 32 + row) << 9);
        for (int j = lane; j < 512; j += 32) {
            float p = srow[j] * inv;
            srow[j] = p;
            prow[j] = p;
        }
    }
    __syncthreads();

    int ql = tid & 31, dg = tid >> 5;
    float a8[8] = {};
    for (int ch = 0; ch < 8; ch++) {
        if (ch < 7) pf(vbase + (size_t)(ch + 1) * 64 * 64, (ch + 1) & 1);
        CP_COMMIT();
        CP_WAIT1();
        __syncthreads();
        const float* kvb = kv + (ch & 1) * KVSZ;
        const float* srow = sc + ql * 513 + ch * 64;
        #pragma unroll 4
        for (int kk = 0; kk < 64; kk++) {
            float s = srow[kk];
            float4 v0 = *(const float4*)(kvb + kk * 68 + dg * 8);
            float4 v1 = *(const float4*)(kvb + kk * 68 + dg * 8 + 4);
            a8[0] = fmaf(s, v0.x, a8[0]); a8[1] = fmaf(s, v0.y, a8[1]);
            a8[2] = fmaf(s, v0.z, a8[2]); a8[3] = fmaf(s, v0.w, a8[3]);
            a8[4] = fmaf(s, v1.x, a8[4]); a8[5] = fmaf(s, v1.y, a8[5]);
            a8[6] = fmaf(s, v1.z, a8[6]); a8[7] = fmaf(s, v1.w, a8[7]);
        }
        __syncthreads();
    }
    size_t o = ((size_t)(b * SS + qb * 32 + ql) << 10) + h * 64 + dg * 8;
    uint32_t ph[4], pl[4];
    #pragma unroll
    for (int i = 0; i < 4; i++) {
        fp16 h0, l0, h1, l1;
        split_fp16(a8[2*i], h0, l0);
        split_fp16(a8[2*i+1], h1, l1);
        ph[i] = ((uint32_t)__half_as_ushort(h1) << 16) | __half_as_ushort(h0);
        pl[i] = ((uint32_t)__half_as_ushort(l1) << 16) | __half_as_ushort(l0);
    }
    *(uint4*)(avh + o) = make_uint4(ph[0], ph[1], ph[2], ph[3]);
    *(uint4*)(avl + o) = make_uint4(pl[0], pl[1], pl[2], pl[3]);
}

// ================= layernorm + fp16 split =================
__global__ __launch_bounds__(256)
void ln_kernel(const float* __restrict__ in, float* __restrict__ out,
               fp16* __restrict__ oh, fp16* __restrict__ ol)
{
    int row = blockIdx.x;
    int tid = threadIdx.x;
    const float* r = in + (size_t)row * DD;
    float v0 = r[tid], v1 = r[tid + 256], v2 = r[tid + 512], v3 = r[tid + 768];
    float s = v0 + v1 + v2 + v3;

    __shared__ float sh[32];
    #pragma unroll
    for (int o = 16; o > 0; o >>= 1) s += __shfl_down_sync(~0u, s, o);
    if ((tid & 31) == 0) sh[tid >> 5] = s;
    __syncthreads();
    if (tid < 8) {
        s = sh[tid];
        #pragma unroll
        for (int o = 4; o > 0; o >>= 1) s += __shfl_down_sync(0xffu, s, o);
        if (tid == 0) sh[0] = s;
    }
    __syncthreads();
    float mean = sh[0] * (1.f / 1024.f);
    float d0 = v0 - mean, d1 = v1 - mean, d2 = v2 - mean, d3 = v3 - mean;
    float qv = d0*d0 + d1*d1 + d2*d2 + d3*d3;
    __syncthreads();
    #pragma unroll
    for (int o = 16; o > 0; o >>= 1) qv += __shfl_down_sync(~0u, qv, o);
    if ((tid & 31) == 0) sh[tid >> 5] = qv;
    __syncthreads();
    if (tid < 8) {
        qv = sh[tid];
        #pragma unroll
        for (int o = 4; o > 0; o >>= 1) qv += __shfl_down_sync(0xffu, qv, o);
        if (tid == 0) sh[0] = qv;
    }
    __syncthreads();
    float inv = rsqrtf(sh[0] * (1.f / 1024.f) + 1e-5f);
    size_t base = (size_t)row * DD;
    #pragma unroll
    for (int jj = 0; jj < 4; jj++) {
        float d = (jj == 0 ? d0 : jj == 1 ? d1 : jj == 2 ? d2 : d3);
        float val = d * inv;
        int idx = tid + jj * 256;
        out[base + idx] = val;
        fp16 h, l; split_fp16(val, h, l);
        oh[base + idx] = h; ol[base + idx] = l;
    }
}

// ================= host driver =================
extern "C" void kernel_launch(void* const* d_in, const int* in_sizes, int n_in,
                              void* d_out, int out_size)
{
    const int*   tok = (const int*)d_in[0];
    const float* we  = (const float*)d_in[1];
    const float* pt  = (const float*)d_in[2];
    const float* Wq  = (const float*)d_in[3];  const float* bq = (const float*)d_in[4];
    const float* Wk  = (const float*)d_in[5];  const float* bk = (const float*)d_in[6];
    const float* Wv  = (const float*)d_in[7];  const float* bv = (const float*)d_in[8];
    const float* Wo  = (const float*)d_in[9];  const float* bo = (const float*)d_in[10];
    const float* W1  = (const float*)d_in[11]; const float* b1 = (const float*)d_in[12];
    const float* W2  = (const float*)d_in[13]; const float* b2 = (const float*)d_in[14];
    float* out = (float*)d_out;

    float *x, *qkv, *yp, *x1p, *bqkv;
    fp16 *xh, *xl, *avh, *avl, *x1h, *x1l, *ffh, *ffl;
    cudaGetSymbolAddress((void**)&x,   g_x);
    cudaGetSymbolAddress((void**)&xh,  g_xh);  cudaGetSymbolAddress((void**)&xl,  g_xl);
    cudaGetSymbolAddress((void**)&qkv, g_qkv);
    cudaGetSymbolAddress((void**)&avh, g_avh); cudaGetSymbolAddress((void**)&avl, g_avl);
    cudaGetSymbolAddress((void**)&yp,  g_y);
    cudaGetSymbolAddress((void**)&x1p, g_x1);
    cudaGetSymbolAddress((void**)&x1h, g_x1h); cudaGetSymbolAddress((void**)&x1l, g_x1l);
    cudaGetSymbolAddress((void**)&ffh, g_ffh); cudaGetSymbolAddress((void**)&ffl, g_ffl);
    cudaGetSymbolAddress((void**)&bqkv, g_bqkv);

    fp16 *wqkvT, *woT, *w1T, *w2T;
    cudaGetSymbolAddress((void**)&wqkvT, g_wqkvT);
    cudaGetSymbolAddress((void**)&woT, g_woT);
    cudaGetSymbolAddress((void**)&w1T, g_w1T);
    cudaGetSymbolAddress((void**)&w2T, g_w2T);

    cudaFuncSetAttribute(gemm_kernel, cudaFuncAttributeMaxDynamicSharedMemorySize, GSMEM);
    cudaFuncSetAttribute(attn_kernel, cudaFuncAttributeMaxDynamicSharedMemorySize, A_TOT * 4);

    static cudaStream_t s2 = nullptr;
    static cudaEvent_t eFork = nullptr, eLay[LL];
    if (!s2) {
        cudaStreamCreate(&s2);
        cudaEventCreateWithFlags(&eFork, cudaEventDisableTiming);
        for (int l = 0; l < LL; l++) cudaEventCreateWithFlags(&eLay[l], cudaEventDisableTiming);
    }

    const size_t PROJ = (size_t)DD * DD;
    const size_t WQKV = (size_t)LL * DD * DD;
    const size_t W1SZ = (size_t)DD * DFF;
    const size_t W2SZ = (size_t)DFF * DD;
    const size_t CORR = (size_t)BB * HH * SS * SS;
    const size_t QKVS = (size_t)MTOK * DD;

    auto split_layer = [&](int l, cudaStream_t st) {
        dim3 gP(DD/32, DD/32);
        wsplit_kernel<<<gP, 256, 0, st>>>(Wq + l*PROJ, wqkvT + l*PROJ,          DD, DD);
        wsplit_kernel<<<gP, 256, 0, st>>>(Wk + l*PROJ, wqkvT + WQKV + l*PROJ,   DD, DD);
        wsplit_kernel<<<gP, 256, 0, st>>>(Wv + l*PROJ, wqkvT + 2*WQKV + l*PROJ, DD, DD);
        wsplit_kernel<<<gP, 256, 0, st>>>(Wo + l*PROJ, woT + l*PROJ, DD, DD);
        dim3 g1(DFF/32, DD/32);
        wsplit_kernel<<<g1, 256, 0, st>>>(W1 + l*W1SZ, w1T + l*W1SZ, DD, DFF);
        dim3 g2(DD/32, DFF/32);
        wsplit_kernel<<<g2, 256, 0, st>>>(W2 + l*W2SZ, w2T + l*W2SZ, DFF, DD);
    };

    bcat_kernel<<<(LL*DD + 255)/256, 256>>>(bq, bk, bv, bqkv, LL*DD);
    split_layer(0, (cudaStream_t)0);
    embed_kernel<<<MTOK, 256>>>(tok, we, pt, x, xh, xl);

    cudaEventRecord(eFork, (cudaStream_t)0);
    cudaStreamWaitEvent(s2, eFork, 0);
    for (int l = 1; l < LL; l++) {
        split_layer(l, s2);
        cudaEventRecord(eLay[l], s2);
    }

    dim3 gQKV(DD / 128, MTOK / 128, 3);   // (8,16,3)
    dim3 gD  (DD / 128, MTOK / 128);      // (8,16)
    dim3 gFF (DFF / 128, MTOK / 128);     // (32,16)
    dim3 gA  (SS / 32, HH, BB);           // (16,16,4)

    float* qp = qkv;
    float* kp = qkv + QKVS;
    float* vp = qkv + 2*QKVS;

    for (int l = 0; l < LL; l++) {
        if (l > 0) cudaStreamWaitEvent((cudaStream_t)0, eLay[l], 0);

        gemm_kernel<<<gQKV, 256, GSMEM>>>(xh, xl, wqkvT + l*PROJ,
                                          bqkv + l*DD, nullptr, qkv, nullptr, nullptr,
                                          DD, DD, 3, WQKV, (size_t)LL*DD, QKVS);

        float* probs_l = out + (size_t)MTOK * DD + (size_t)l * CORR;
        attn_kernel<<<gA, 256, A_TOT*4>>>(qp, kp, vp, tok, probs_l, avh, avl);

        gemm_kernel<<<gD, 256, GSMEM>>>(avh, avl, woT + l*PROJ, bo + l*DD,
                                        x, yp, nullptr, nullptr, DD, DD, 2, 0, 0, 0);
        ln_kernel<<<MTOK, 256>>>(yp, x1p, x1h, x1l);

        gemm_kernel<<<gFF, 256, GSMEM>>>(x1h, x1l, w1T + l*W1SZ, b1 + l*DFF,
                                         nullptr, nullptr, ffh, ffl, DD, DFF, 1, 0, 0, 0);
        gemm_kernel<<<gD, 256, GSMEM>>>(ffh, ffl, w2T + l*W2SZ, b2 + l*DD,
                                        x1p, yp, nullptr, nullptr, DFF, DD, 2, 0, 0, 0);

        float* xdst = (l == LL - 1) ? out : x;
        ln_kernel<<<MTOK, 256>>>(yp, xdst, xh, xl);
    }
}

// round 7
// speedup vs baseline: 1.4497x; 1.1252x over previous
#include <cuda_runtime.h>
#include <cuda_fp16.h>
#include <math.h>
#include <stdint.h>

// Problem constants
#define BB 4
#define SS 512
#define DD 1024
#define HH 16
#define DHH 64
#define DFF 4096
#define LL 6
#define MTOK (BB*SS)          // 2048 token rows

typedef __half fp16;

// ================= device scratch =================
__device__ float g_x  [MTOK*DD];
__device__ fp16  g_xh [MTOK*DD],  g_xl [MTOK*DD];
__device__ fp16  g_qh [MTOK*DD],  g_ql [MTOK*DD];   // Q fp16 split [B,H,S,64]
__device__ fp16  g_kh [MTOK*DD];                    // K fp16 [B,H,S,64]
__device__ float g_v  [MTOK*DD];                    // V fp32 [B,H,S,64]
__device__ fp16  g_avh[MTOK*DD],  g_avl[MTOK*DD];
__device__ float g_y  [MTOK*DD];
__device__ float g_x1 [MTOK*DD];
__device__ fp16  g_x1h[MTOK*DD],  g_x1l[MTOK*DD];
__device__ fp16  g_ffh[MTOK*DFF], g_ffl[MTOK*DFF];

__device__ fp16 g_wqkvT[3*LL*DD*DD];   // [3][L][N][K]
__device__ fp16 g_woT[LL*DD*DD];
__device__ fp16 g_w1T[LL*DD*DFF];
__device__ fp16 g_w2T[LL*DFF*DD];
__device__ float g_bqkv[3*LL*DD];

// ================= helpers =================
__device__ __forceinline__ uint32_t smem_u32(const void* p) {
    uint32_t a;
    asm("{ .reg .u64 t; cvta.to.shared.u64 t, %1; cvt.u32.u64 %0, t; }" : "=r"(a) : "l"(p));
    return a;
}
__device__ __forceinline__ void split_fp16(float v, fp16& h, fp16& l) {
    h = __float2half_rn(v);
    l = __float2half_rn(v - __half2float(h));
}

#define CP_ASYNC16(sa, ga) \
    asm volatile("cp.async.cg.shared.global [%0], [%1], 16;" :: "r"(sa), "l"(ga) : "memory")
#define CP_COMMIT() asm volatile("cp.async.commit_group;" ::: "memory")
#define CP_WAIT1()  asm volatile("cp.async.wait_group 1;" ::: "memory")

#define LDSM_X4(r0,r1,r2,r3, addr) \
    asm volatile("ldmatrix.sync.aligned.m8n8.x4.shared.b16 {%0,%1,%2,%3}, [%4];" \
        : "=r"(r0), "=r"(r1), "=r"(r2), "=r"(r3) : "r"(addr))

#define MMA_F16(d, a, b0, b1) \
    asm volatile("mma.sync.aligned.m16n8k16.row.col.f32.f16.f16.f32 " \
        "{%0,%1,%2,%3}, {%4,%5,%6,%7}, {%8,%9}, {%0,%1,%2,%3};" \
        : "+f"((d)[0]), "+f"((d)[1]), "+f"((d)[2]), "+f"((d)[3]) \
        : "r"((a)[0]), "r"((a)[1]), "r"((a)[2]), "r"((a)[3]), "r"(b0), "r"(b1))

// ================= embedding =================
__global__ void embed_kernel(const int* __restrict__ tok,
                             const float* __restrict__ we,
                             const float* __restrict__ pt,
                             float* __restrict__ x,
                             fp16* __restrict__ xh, fp16* __restrict__ xl)
{
    int m = blockIdx.x;
    int t = tok[m];
    const float* wr = we + (size_t)t * DD;
    const float* pr = pt + (size_t)t * DD;
    size_t base = (size_t)m * DD;
    for (int j = threadIdx.x; j < DD; j += blockDim.x) {
        float v = wr[j] + pr[j];
        x[base + j] = v;
        fp16 h, l; split_fp16(v, h, l);
        xh[base + j] = h; xl[base + j] = l;
    }
}

// ========== weight transpose + fp16 round ==========
__global__ __launch_bounds__(256)
void wsplit_kernel(const float* __restrict__ W, fp16* __restrict__ Th, int K, int N)
{
    __shared__ float s[32][33];
    int nb = blockIdx.x * 32, kb = blockIdx.y * 32;
    int tx = threadIdx.x & 31, ty = threadIdx.x >> 5;
    #pragma unroll
    for (int j = 0; j < 4; j++)
        s[ty + 8*j][tx] = W[(size_t)(kb + ty + 8*j) * N + nb + tx];
    __syncthreads();
    #pragma unroll
    for (int j = 0; j < 4; j++) {
        float v = s[tx][ty + 8*j];
        Th[(size_t)(nb + ty + 8*j) * K + kb + tx] = __float2half_rn(v);
    }
}

__global__ void bcat_kernel(const float* __restrict__ a, const float* __restrict__ b,
                            const float* __restrict__ c, float* __restrict__ dst, int n)
{
    int i = blockIdx.x * blockDim.x + threadIdx.x;
    if (i < n) { dst[i] = a[i]; dst[n + i] = b[i]; dst[2*n + i] = c[i]; }
}

// ================= fp16x2 mma.sync GEMM, templated tile-M =================
// BM in {128,64}. BK=32, 3-stage cp.async pipeline, 2 CTAs/SM.
// mode 0: fp32+bias; 1: relu->fp16 h/l; 2: +bias+Res->fp32;
// mode 3: QKV: z=0 -> Ch/Cl fp16 split remap, z=1 -> Khp fp16 remap, z=2 -> C fp32 remap.
template<int BM>
__global__ __launch_bounds__(256, 2)
void gemm_kernel(const fp16* __restrict__ Ah, const fp16* __restrict__ Al,
                 const fp16* __restrict__ Bh_,
                 const float* __restrict__ bias_, const float* __restrict__ Res,
                 float* __restrict__ C_, fp16* __restrict__ Ch, fp16* __restrict__ Cl,
                 fp16* __restrict__ Khp,
                 int K, int N, int mode, size_t zsB, size_t zsBias)
{
    constexpr int SA = BM * 64;            // bytes per A array per stage
    constexpr int STAGE = 2 * SA + 8192;   // Ah + Al + B(128x32 fp16)
    constexpr int NP = (BM == 128) ? 4 : 2;

    extern __shared__ char smem[];
    const uint32_t sb = smem_u32(smem);
    const int tid = threadIdx.x;
    const int lane = tid & 31, wid = tid >> 5;
    const int WM = (BM == 128) ? (wid & 3) : (wid & 1);
    const int WN = (BM == 128) ? (wid >> 2) : (wid >> 1);
    const int m0 = blockIdx.y * BM, n0 = blockIdx.x * 128;

    const fp16* Bh = Bh_ + blockIdx.z * zsB;
    const float* bias = bias_ + blockIdx.z * zsBias;

    int lrow0 = tid >> 2, lkg0 = tid & 3;
    int lrow1 = (tid + 256) >> 2;
    uint32_t soff0 = (uint32_t)(lrow0 * 64 + ((lkg0 ^ ((lrow0 >> 1) & 3)) << 4));
    uint32_t soff1 = (uint32_t)(lrow1 * 64 + ((lkg0 ^ ((lrow1 >> 1) & 3)) << 4));

    const fp16* gAh = Ah + (size_t)(m0 + lrow0) * K + lkg0 * 8;
    const fp16* gAl = Al + (size_t)(m0 + lrow0) * K + lkg0 * 8;
    const fp16* gBh = Bh + (size_t)(n0 + lrow0) * K + lkg0 * 8;
    const fp16* gAh1 = Ah + (size_t)(m0 + (BM == 128 ? lrow1 : lrow0)) * K + lkg0 * 8;
    const fp16* gAl1 = Al + (size_t)(m0 + (BM == 128 ? lrow1 : lrow0)) * K + lkg0 * 8;
    const fp16* gBh1 = Bh + (size_t)(n0 + lrow1) * K + lkg0 * 8;

    int matA = lane >> 3;
    int arow_local = ((matA & 1) << 3) + (lane & 7);
    int akgbit = matA >> 1;
    uint32_t offA[2][2];
    #pragma unroll
    for (int mt = 0; mt < 2; mt++) {
        int row = WM * 32 + mt * 16 + arow_local;
        int swz = (row >> 1) & 3;
        #pragma unroll
        for (int ks = 0; ks < 2; ks++)
            offA[mt][ks] = (uint32_t)(row * 64 + (((ks * 2 + akgbit) ^ swz) << 4));
    }
    int brow_local = ((matA >> 1) << 3) + (lane & 7);
    int bkgbit = matA & 1;
    uint32_t offB[NP][2];
    #pragma unroll
    for (int np = 0; np < NP; np++) {
        int row = WN * (NP * 16) + np * 16 + brow_local;
        int swz = (row >> 1) & 3;
        #pragma unroll
        for (int ks = 0; ks < 2; ks++)
            offB[np][ks] = (uint32_t)(row * 64 + (((ks * 2 + bkgbit) ^ swz) << 4));
    }

    float acc[2][2*NP][4];
    #pragma unroll
    for (int i = 0; i < 2; i++)
        #pragma unroll
        for (int j = 0; j < 2*NP; j++)
            #pragma unroll
            for (int qq = 0; qq < 4; qq++) acc[i][j][qq] = 0.f;

    const int NC = K >> 5;

    auto load_stage = [&](int stage, int chunk) {
        uint32_t base = sb + stage * STAGE;
        size_t gk = (size_t)(chunk << 5);
        CP_ASYNC16(base            + soff0, gAh  + gk);
        CP_ASYNC16(base + SA       + soff0, gAl  + gk);
        CP_ASYNC16(base + 2*SA     + soff0, gBh  + gk);
        if (BM == 128) {
            CP_ASYNC16(base        + soff1, gAh1 + gk);
            CP_ASYNC16(base + SA   + soff1, gAl1 + gk);
        }
        CP_ASYNC16(base + 2*SA     + soff1, gBh1 + gk);
    };

    load_stage(0, 0); CP_COMMIT();
    if (NC > 1) load_stage(1, 1);
    CP_COMMIT();

    int cur = 0;
    for (int i = 0; i < NC; i++) {
        CP_WAIT1();
        __syncthreads();

        uint32_t base = sb + cur * STAGE;
        uint32_t sAh = base, sAl = base + SA, sBh = base + 2*SA;

        #pragma unroll
        for (int ks = 0; ks < 2; ks++) {
            uint32_t ah[2][4], al[2][4];
            #pragma unroll
            for (int mt = 0; mt < 2; mt++) {
                LDSM_X4(ah[mt][0], ah[mt][1], ah[mt][2], ah[mt][3], sAh + offA[mt][ks]);
                LDSM_X4(al[mt][0], al[mt][1], al[mt][2], al[mt][3], sAl + offA[mt][ks]);
            }
            #pragma unroll
            for (int np = 0; np < NP; np++) {
                uint32_t bh[4];
                LDSM_X4(bh[0], bh[1], bh[2], bh[3], sBh + offB[np][ks]);
                #pragma unroll
                for (int mt = 0; mt < 2; mt++) {
                    MMA_F16(acc[mt][np*2+0], ah[mt], bh[0], bh[1]);
                    MMA_F16(acc[mt][np*2+0], al[mt], bh[0], bh[1]);
                    MMA_F16(acc[mt][np*2+1], ah[mt], bh[2], bh[3]);
                    MMA_F16(acc[mt][np*2+1], al[mt], bh[2], bh[3]);
                }
            }
        }
        __syncthreads();
        if (i + 2 < NC) {
            int pf = cur + 2; if (pf >= 3) pf -= 3;
            load_stage(pf, i + 2);
        }
        CP_COMMIT();
        cur = (cur + 1 == 3) ? 0 : cur + 1;
    }

    // -------- epilogue --------
    #pragma unroll
    for (int mt = 0; mt < 2; mt++) {
        int r0 = m0 + WM * 32 + mt * 16 + (lane >> 2);
        int r1 = r0 + 8;
        #pragma unroll
        for (int nt = 0; nt < 2*NP; nt++) {
            int c = n0 + WN * (NP * 16) + nt * 8 + ((lane & 3) << 1);
            float2 bv = *(const float2*)(bias + c);
            float v00 = acc[mt][nt][0] + bv.x, v01 = acc[mt][nt][1] + bv.y;
            float v10 = acc[mt][nt][2] + bv.x, v11 = acc[mt][nt][3] + bv.y;
            if (mode == 0) {
                *(float2*)(C_ + (size_t)r0 * N + c) = make_float2(v00, v01);
                *(float2*)(C_ + (size_t)r1 * N + c) = make_float2(v10, v11);
            } else if (mode == 1) {
                v00 = fmaxf(v00, 0.f); v01 = fmaxf(v01, 0.f);
                v10 = fmaxf(v10, 0.f); v11 = fmaxf(v11, 0.f);
                fp16 h0,l0,h1,l1,h2,l2,h3,l3;
                split_fp16(v00,h0,l0); split_fp16(v01,h1,l1);
                split_fp16(v10,h2,l2); split_fp16(v11,h3,l3);
                *(__half2*)(Ch + (size_t)r0 * N + c) = __halves2half2(h0, h1);
                *(__half2*)(Cl + (size_t)r0 * N + c) = __halves2half2(l0, l1);
                *(__half2*)(Ch + (size_t)r1 * N + c) = __halves2half2(h2, h3);
                *(__half2*)(Cl + (size_t)r1 * N + c) = __halves2half2(l2, l3);
            } else if (mode == 2) {
                float2 q0 = *(const float2*)(Res + (size_t)r0 * N + c);
                float2 q1 = *(const float2*)(Res + (size_t)r1 * N + c);
                *(float2*)(C_ + (size_t)r0 * N + c) = make_float2(v00 + q0.x, v01 + q0.y);
                *(float2*)(C_ + (size_t)r1 * N + c) = make_float2(v10 + q1.x, v11 + q1.y);
            } else {
                // QKV remap: m=(b,s), n=(h,d) -> [B,H,S,64]
                int b0_ = r0 >> 9, s0_ = r0 & 511;
                int b1_ = r1 >> 9, s1_ = r1 & 511;
                int h_ = c >> 6, d_ = c & 63;
                size_t i0 = ((((size_t)b0_ * HH + h_) * SS + s0_) << 6) + d_;
                size_t i1 = ((((size_t)b1_ * HH + h_) * SS + s1_) << 6) + d_;
                int z = blockIdx.z;
                if (z == 0) {
                    fp16 h0,l0,h1,l1,h2,l2,h3,l3;
                    split_fp16(v00,h0,l0); split_fp16(v01,h1,l1);
                    split_fp16(v10,h2,l2); split_fp16(v11,h3,l3);
                    *(__half2*)(Ch + i0) = __halves2half2(h0, h1);
                    *(__half2*)(Cl + i0) = __halves2half2(l0, l1);
                    *(__half2*)(Ch + i1) = __halves2half2(h2, h3);
                    *(__half2*)(Cl + i1) = __halves2half2(l2, l3);
                } else if (z == 1) {
                    *(__half2*)(Khp + i0) = __halves2half2(__float2half_rn(v00), __float2half_rn(v01));
                    *(__half2*)(Khp + i1) = __halves2half2(__float2half_rn(v10), __float2half_rn(v11));
                } else {
                    *(float2*)(C_ + i0) = make_float2(v00, v01);
                    *(float2*)(C_ + i1) = make_float2(v10, v11);
                }
            }
        }
    }
}

// ================= fused attention: tensor-core scores + fp32 softmax/AV =================
// smem bytes: sc fp32[32][513] | regionA 24KB (Qh 4K | Ql 4K | Kbuf[2] 8K each) or Vbuf0 | regionB 17408 (Vbuf1)
#define SC_B   0
#define RA_B   (32*513*4)              // 65664
#define RB_B   (RA_B + 24576)          // 90240
#define ATT_SMEM (RB_B + 17408)        // 107648

__global__ __launch_bounds__(256, 2)
void attn_kernel(const fp16* __restrict__ qh, const fp16* __restrict__ ql,
                 const fp16* __restrict__ kh, const float* __restrict__ v,
                 const int* __restrict__ tok,
                 float* __restrict__ probs, fp16* __restrict__ avh, fp16* __restrict__ avl)
{
    extern __shared__ char smc[];
    float* sm = (float*)smc;
    float* sc = sm;                        // 32 x 513
    const uint32_t sb = smem_u32(smc);
    int qb = blockIdx.x, h = blockIdx.y, b = blockIdx.z;
    int tid = threadIdx.x;
    int w = tid >> 5, lane = tid & 31;

    const size_t bh_off = (((size_t)b * HH + h) * SS) << 6;
    const fp16* qh_g = qh + bh_off + ((size_t)qb * 32 << 6);
    const fp16* ql_g = ql + bh_off + ((size_t)qb * 32 << 6);
    const fp16* kh_g = kh + bh_off;
    const float* v_g = v + bh_off;
    const int* tb = tok + b * SS;

    // ---- async loads: Q (h/l) once, K in 64-key chunks ----
    auto pf_k = [&](int ch, int buf) {
        uint32_t sdst = sb + RA_B + 8192 + buf * 8192;
        const fp16* src = kh_g + (size_t)(ch * 64) * 64;
        #pragma unroll
        for (int t = 0; t < 2; t++) {
            int j = tid + 256 * t;
            int row = j >> 3, kg = j & 7;
            CP_ASYNC16(sdst + (uint32_t)(row * 128 + ((kg ^ (row & 7)) << 4)),
                       src + (size_t)row * 64 + kg * 8);
        }
    };
    {
        int row = tid >> 3, kg = tid & 7;
        uint32_t so = (uint32_t)(row * 128 + ((kg ^ (row & 7)) << 4));
        CP_ASYNC16(sb + RA_B + so,        qh_g + (size_t)row * 64 + kg * 8);
        CP_ASYNC16(sb + RA_B + 4096 + so, ql_g + (size_t)row * 64 + kg * 8);
    }
    pf_k(0, 0);
    CP_COMMIT();

    // ---- per-warp MMA mapping: warp = (q-half, key-quarter) ----
    int qh16 = (w >> 2) * 16;      // 0 / 16
    int keyq = w & 3;              // 16 keys
    int matA = lane >> 3;
    int arow = qh16 + ((matA & 1) << 3) + (lane & 7);
    int akg = matA >> 1;
    uint32_t offQ[4];
    #pragma unroll
    for (int ks = 0; ks < 4; ks++)
        offQ[ks] = (uint32_t)(arow * 128 + (((ks * 2 + akg) ^ (arow & 7)) << 4));
    int brow = keyq * 16 + ((matA >> 1) << 3) + (lane & 7);
    int bkg = matA & 1;
    uint32_t offK[4];
    #pragma unroll
    for (int ks = 0; ks < 4; ks++)
        offK[ks] = (uint32_t)(brow * 128 + (((ks * 2 + bkg) ^ (brow & 7)) << 4));

    const uint32_t qhb = sb + RA_B, qlb = sb + RA_B + 4096;

    // ---- scores: 8 chunks of 64 keys ----
    for (int ch = 0; ch < 8; ch++) {
        if (ch < 7) pf_k(ch + 1, (ch + 1) & 1);
        CP_COMMIT();
        CP_WAIT1();
        __syncthreads();
        uint32_t kb = sb + RA_B + 8192 + (ch & 1) * 8192;

        float c0[4] = {0.f,0.f,0.f,0.f}, c1[4] = {0.f,0.f,0.f,0.f};
        #pragma unroll
        for (int ks = 0; ks < 4; ks++) {
            uint32_t ah[4], al[4], bb[4];
            LDSM_X4(ah[0], ah[1], ah[2], ah[3], qhb + offQ[ks]);
            LDSM_X4(al[0], al[1], al[2], al[3], qlb + offQ[ks]);
            LDSM_X4(bb[0], bb[1], bb[2], bb[3], kb + offK[ks]);
            MMA_F16(c0, ah, bb[0], bb[1]);
            MMA_F16(c0, al, bb[0], bb[1]);
            MMA_F16(c1, ah, bb[2], bb[3]);
            MMA_F16(c1, al, bb[2], bb[3]);
        }
        // writeback fragments -> sc with mask + scale
        int tc = lane >> 2, tcol = (lane & 3) * 2;
        int q0 = qh16 + tc, q1 = q0 + 8;
        #pragma unroll
        for (int nt = 0; nt < 2; nt++) {
            float* cc = nt ? c1 : c0;
            int key0 = ch * 64 + keyq * 16 + nt * 8 + tcol;
            bool m0 = (tb[key0] == 0), m1 = (tb[key0 + 1] == 0);
            sc[q0 * 513 + key0]     = m0 ? -INFINITY : cc[0] * 0.125f;
            sc[q0 * 513 + key0 + 1] = m1 ? -INFINITY : cc[1] * 0.125f;
            sc[q1 * 513 + key0]     = m0 ? -INFINITY : cc[2] * 0.125f;
            sc[q1 * 513 + key0 + 1] = m1 ? -INFINITY : cc[3] * 0.125f;
        }
        __syncthreads();
    }

    // ---- prefetch V chunk 0 (regionA free now) ----
    auto pf_v = [&](const float* gsrc, int buf) {
        uint32_t sdst = sb + (buf ? RB_B : RA_B);
        #pragma unroll
        for (int t = 0; t < 4; t++) {
            int j = tid + 256 * t;
            int row = j >> 4, c4 = j & 15;
            CP_ASYNC16(sdst + (uint32_t)(row * 68 + c4 * 4) * 4,
                       gsrc + (size_t)row * 64 + c4 * 4);
        }
    };
    pf_v(v_g, 0); CP_COMMIT();

    // ---- softmax: 8 warps x 4 rows ----
    #pragma unroll 1
    for (int rr = 0; rr < 4; rr++) {
        int row = w * 4 + rr;
        float* srow = sc + row * 513;
        float m = -INFINITY;
        for (int j = lane; j < 512; j += 32) m = fmaxf(m, srow[j]);
        #pragma unroll
        for (int o = 16; o > 0; o >>= 1) m = fmaxf(m, __shfl_xor_sync(~0u, m, o));
        float sum = 0.f;
        for (int j = lane; j < 512; j += 32) {
            float e = __expf(srow[j] - m);
            srow[j] = e; sum += e;
        }
        #pragma unroll
        for (int o = 16; o > 0; o >>= 1) sum += __shfl_xor_sync(~0u, sum, o);
        float inv = 1.f / sum;
        float* prow = probs + ((((size_t)b * HH + h) * SS + qb * 32 + row) << 9);
        for (int j = lane; j < 512; j += 32) {
            float p = srow[j] * inv;
            srow[j] = p;
            prow[j] = p;
        }
    }
    __syncthreads();

    // ---- AV: double-buffered V (fp32) ----
    int ql_ = tid & 31, dg = tid >> 5;
    float a8[8] = {};
    for (int ch = 0; ch < 8; ch++) {
        if (ch < 7) pf_v(v_g + (size_t)(ch + 1) * 64 * 64, (ch + 1) & 1);
        CP_COMMIT();
        CP_WAIT1();
        __syncthreads();
        const float* kvb = sm + ((ch & 1) ? (RB_B >> 2) : (RA_B >> 2));
        const float* srow = sc + ql_ * 513 + ch * 64;
        #pragma unroll 4
        for (int kk = 0; kk < 64; kk++) {
            float s = srow[kk];
            float4 v0 = *(const float4*)(kvb + kk * 68 + dg * 8);
            float4 v1 = *(const float4*)(kvb + kk * 68 + dg * 8 + 4);
            a8[0] = fmaf(s, v0.x, a8[0]); a8[1] = fmaf(s, v0.y, a8[1]);
            a8[2] = fmaf(s, v0.z, a8[2]); a8[3] = fmaf(s, v0.w, a8[3]);
            a8[4] = fmaf(s, v1.x, a8[4]); a8[5] = fmaf(s, v1.y, a8[5]);
            a8[6] = fmaf(s, v1.z, a8[6]); a8[7] = fmaf(s, v1.w, a8[7]);
        }
        __syncthreads();
    }
    size_t o = ((size_t)(b * SS + qb * 32 + ql_) << 10) + h * 64 + dg * 8;
    uint32_t ph[4], pl[4];
    #pragma unroll
    for (int i = 0; i < 4; i++) {
        fp16 h0, l0, h1, l1;
        split_fp16(a8[2*i], h0, l0);
        split_fp16(a8[2*i+1], h1, l1);
        ph[i] = ((uint32_t)__half_as_ushort(h1) << 16) | __half_as_ushort(h0);
        pl[i] = ((uint32_t)__half_as_ushort(l1) << 16) | __half_as_ushort(l0);
    }
    *(uint4*)(avh + o) = make_uint4(ph[0], ph[1], ph[2], ph[3]);
    *(uint4*)(avl + o) = make_uint4(pl[0], pl[1], pl[2], pl[3]);
}

// ================= layernorm + fp16 split =================
__global__ __launch_bounds__(256)
void ln_kernel(const float* __restrict__ in, float* __restrict__ out,
               fp16* __restrict__ oh, fp16* __restrict__ ol)
{
    int row = blockIdx.x;
    int tid = threadIdx.x;
    const float* r = in + (size_t)row * DD;
    float v0 = r[tid], v1 = r[tid + 256], v2 = r[tid + 512], v3 = r[tid + 768];
    float s = v0 + v1 + v2 + v3;

    __shared__ float sh[32];
    #pragma unroll
    for (int o = 16; o > 0; o >>= 1) s += __shfl_down_sync(~0u, s, o);
    if ((tid & 31) == 0) sh[tid >> 5] = s;
    __syncthreads();
    if (tid < 8) {
        s = sh[tid];
        #pragma unroll
        for (int o = 4; o > 0; o >>= 1) s += __shfl_down_sync(0xffu, s, o);
        if (tid == 0) sh[0] = s;
    }
    __syncthreads();
    float mean = sh[0] * (1.f / 1024.f);
    float d0 = v0 - mean, d1 = v1 - mean, d2 = v2 - mean, d3 = v3 - mean;
    float qv = d0*d0 + d1*d1 + d2*d2 + d3*d3;
    __syncthreads();
    #pragma unroll
    for (int o = 16; o > 0; o >>= 1) qv += __shfl_down_sync(~0u, qv, o);
    if ((tid & 31) == 0) sh[tid >> 5] = qv;
    __syncthreads();
    if (tid < 8) {
        qv = sh[tid];
        #pragma unroll
        for (int o = 4; o > 0; o >>= 1) qv += __shfl_down_sync(0xffu, qv, o);
        if (tid == 0) sh[0] = qv;
    }
    __syncthreads();
    float inv = rsqrtf(sh[0] * (1.f / 1024.f) + 1e-5f);
    size_t base = (size_t)row * DD;
    #pragma unroll
    for (int jj = 0; jj < 4; jj++) {
        float d = (jj == 0 ? d0 : jj == 1 ? d1 : jj == 2 ? d2 : d3);
        float val = d * inv;
        int idx = tid + jj * 256;
        out[base + idx] = val;
        fp16 h, l; split_fp16(val, h, l);
        oh[base + idx] = h; ol[base + idx] = l;
    }
}

// ================= host driver =================
extern "C" void kernel_launch(void* const* d_in, const int* in_sizes, int n_in,
                              void* d_out, int out_size)
{
    const int*   tok = (const int*)d_in[0];
    const float* we  = (const float*)d_in[1];
    const float* pt  = (const float*)d_in[2];
    const float* Wq  = (const float*)d_in[3];  const float* bq = (const float*)d_in[4];
    const float* Wk  = (const float*)d_in[5];  const float* bk = (const float*)d_in[6];
    const float* Wv  = (const float*)d_in[7];  const float* bv = (const float*)d_in[8];
    const float* Wo  = (const float*)d_in[9];  const float* bo = (const float*)d_in[10];
    const float* W1  = (const float*)d_in[11]; const float* b1 = (const float*)d_in[12];
    const float* W2  = (const float*)d_in[13]; const float* b2 = (const float*)d_in[14];
    float* out = (float*)d_out;

    float *x, *yp, *x1p, *bqkv, *vf;
    fp16 *xh, *xl, *qhp, *qlp, *khp, *avh, *avl, *x1h, *x1l, *ffh, *ffl;
    cudaGetSymbolAddress((void**)&x,   g_x);
    cudaGetSymbolAddress((void**)&xh,  g_xh);  cudaGetSymbolAddress((void**)&xl,  g_xl);
    cudaGetSymbolAddress((void**)&qhp, g_qh);  cudaGetSymbolAddress((void**)&qlp, g_ql);
    cudaGetSymbolAddress((void**)&khp, g_kh);  cudaGetSymbolAddress((void**)&vf,  g_v);
    cudaGetSymbolAddress((void**)&avh, g_avh); cudaGetSymbolAddress((void**)&avl, g_avl);
    cudaGetSymbolAddress((void**)&yp,  g_y);
    cudaGetSymbolAddress((void**)&x1p, g_x1);
    cudaGetSymbolAddress((void**)&x1h, g_x1h); cudaGetSymbolAddress((void**)&x1l, g_x1l);
    cudaGetSymbolAddress((void**)&ffh, g_ffh); cudaGetSymbolAddress((void**)&ffl, g_ffl);
    cudaGetSymbolAddress((void**)&bqkv, g_bqkv);

    fp16 *wqkvT, *woT, *w1T, *w2T;
    cudaGetSymbolAddress((void**)&wqkvT, g_wqkvT);
    cudaGetSymbolAddress((void**)&woT, g_woT);
    cudaGetSymbolAddress((void**)&w1T, g_w1T);
    cudaGetSymbolAddress((void**)&w2T, g_w2T);

    const int GS128 = 3 * (2 * 128 * 64 + 8192);   // 73728
    const int GS64  = 3 * (2 * 64 * 64 + 8192);    // 49152
    cudaFuncSetAttribute(gemm_kernel<128>, cudaFuncAttributeMaxDynamicSharedMemorySize, GS128);
    cudaFuncSetAttribute(gemm_kernel<64>,  cudaFuncAttributeMaxDynamicSharedMemorySize, GS64);
    cudaFuncSetAttribute(attn_kernel, cudaFuncAttributeMaxDynamicSharedMemorySize, ATT_SMEM);

    static cudaStream_t s2 = nullptr;
    static cudaEvent_t eFork = nullptr, eLay[LL];
    if (!s2) {
        cudaStreamCreate(&s2);
        cudaEventCreateWithFlags(&eFork, cudaEventDisableTiming);
        for (int l = 0; l < LL; l++) cudaEventCreateWithFlags(&eLay[l], cudaEventDisableTiming);
    }

    const size_t PROJ = (size_t)DD * DD;
    const size_t WQKV = (size_t)LL * DD * DD;
    const size_t W1SZ = (size_t)DD * DFF;
    const size_t W2SZ = (size_t)DFF * DD;
    const size_t CORR = (size_t)BB * HH * SS * SS;

    auto split_layer = [&](int l, cudaStream_t st) {
        dim3 gP(DD/32, DD/32);
        wsplit_kernel<<<gP, 256, 0, st>>>(Wq + l*PROJ, wqkvT + l*PROJ,          DD, DD);
        wsplit_kernel<<<gP, 256, 0, st>>>(Wk + l*PROJ, wqkvT + WQKV + l*PROJ,   DD, DD);
        wsplit_kernel<<<gP, 256, 0, st>>>(Wv + l*PROJ, wqkvT + 2*WQKV + l*PROJ, DD, DD);
        wsplit_kernel<<<gP, 256, 0, st>>>(Wo + l*PROJ, woT + l*PROJ, DD, DD);
        dim3 g1(DFF/32, DD/32);
        wsplit_kernel<<<g1, 256, 0, st>>>(W1 + l*W1SZ, w1T + l*W1SZ, DD, DFF);
        dim3 g2(DD/32, DFF/32);
        wsplit_kernel<<<g2, 256, 0, st>>>(W2 + l*W2SZ, w2T + l*W2SZ, DFF, DD);
    };

    bcat_kernel<<<(LL*DD + 255)/256, 256>>>(bq, bk, bv, bqkv, LL*DD);
    split_layer(0, (cudaStream_t)0);
    embed_kernel<<<MTOK, 256>>>(tok, we, pt, x, xh, xl);

    cudaEventRecord(eFork, (cudaStream_t)0);
    cudaStreamWaitEvent(s2, eFork, 0);
    for (int l = 1; l < LL; l++) {
        split_layer(l, s2);
        cudaEventRecord(eLay[l], s2);
    }

    dim3 gQKV(DD / 128, MTOK / 128, 3);   // (8,16,3)
    dim3 gFF (DFF / 128, MTOK / 128);     // (32,16)
    dim3 gD64(DD / 128, MTOK / 64);       // (8,32) = 256 CTAs
    dim3 gA  (SS / 32, HH, BB);           // (16,16,4)

    for (int l = 0; l < LL; l++) {
        if (l > 0) cudaStreamWaitEvent((cudaStream_t)0, eLay[l], 0);

        gemm_kernel<128><<<gQKV, 256, GS128>>>(xh, xl, wqkvT + l*PROJ,
                                          bqkv + l*DD, nullptr, vf, qhp, qlp, khp,
                                          DD, DD, 3, WQKV, (size_t)LL*DD);

        float* probs_l = out + (size_t)MTOK * DD + (size_t)l * CORR;
        attn_kernel<<<gA, 256, ATT_SMEM>>>(qhp, qlp, khp, vf, tok, probs_l, avh, avl);

        gemm_kernel<64><<<gD64, 256, GS64>>>(avh, avl, woT + l*PROJ, bo + l*DD,
                                        x, yp, nullptr, nullptr, nullptr, DD, DD, 2, 0, 0);
        ln_kernel<<<MTOK, 256>>>(yp, x1p, x1h, x1l);

        gemm_kernel<128><<<gFF, 256, GS128>>>(x1h, x1l, w1T + l*W1SZ, b1 + l*DFF,
                                         nullptr, nullptr, ffh, ffl, nullptr, DD, DFF, 1, 0, 0);
        gemm_kernel<64><<<gD64, 256, GS64>>>(ffh, ffl, w2T + l*W2SZ, b2 + l*DD,
                                        x1p, yp, nullptr, nullptr, nullptr, DFF, DD, 2, 0, 0);

        float* xdst = (l == LL - 1) ? out : x;
        ln_kernel<<<MTOK, 256>>>(yp, xdst, xh, xl);
    }
}

// round 8
// speedup vs baseline: 1.5754x; 1.0867x over previous
#include <cuda_runtime.h>
#include <cuda_fp16.h>
#include <math.h>
#include <stdint.h>

// Problem constants
#define BB 4
#define SS 512
#define DD 1024
#define HH 16
#define DHH 64
#define DFF 4096
#define LL 6
#define MTOK (BB*SS)          // 2048 token rows

typedef __half fp16;

// ================= device scratch =================
__device__ float g_x  [MTOK*DD];
__device__ fp16  g_xh [MTOK*DD],  g_xl [MTOK*DD];
__device__ fp16  g_qh [MTOK*DD],  g_ql [MTOK*DD];   // Q fp16 split [B,H,S,64]
__device__ fp16  g_kh [MTOK*DD];                    // K fp16 [B,H,S,64]
__device__ float g_v  [MTOK*DD];                    // V fp32 [B,H,S,64]
__device__ fp16  g_avh[MTOK*DD],  g_avl[MTOK*DD];
__device__ float g_y  [MTOK*DD];
__device__ float g_x1 [MTOK*DD];
__device__ fp16  g_x1h[MTOK*DD],  g_x1l[MTOK*DD];
__device__ fp16  g_ffh[MTOK*DFF], g_ffl[MTOK*DFF];

__device__ fp16 g_wqkvT[3*LL*DD*DD];   // [3][L][N][K]
__device__ fp16 g_woT[LL*DD*DD];
__device__ fp16 g_w1T[LL*DD*DFF];
__device__ fp16 g_w2T[LL*DFF*DD];
__device__ float g_bqkv[3*LL*DD];

// ================= helpers =================
__device__ __forceinline__ uint32_t smem_u32(const void* p) {
    uint32_t a;
    asm("{ .reg .u64 t; cvta.to.shared.u64 t, %1; cvt.u32.u64 %0, t; }" : "=r"(a) : "l"(p));
    return a;
}
__device__ __forceinline__ void split_fp16(float v, fp16& h, fp16& l) {
    h = __float2half_rn(v);
    l = __float2half_rn(v - __half2float(h));
}

#define CP_ASYNC16(sa, ga) \
    asm volatile("cp.async.cg.shared.global [%0], [%1], 16;" :: "r"(sa), "l"(ga) : "memory")
#define CP_COMMIT() asm volatile("cp.async.commit_group;" ::: "memory")
#define CP_WAIT1()  asm volatile("cp.async.wait_group 1;" ::: "memory")
#define CP_WAIT0()  asm volatile("cp.async.wait_group 0;" ::: "memory")

#define LDSM_X4(r0,r1,r2,r3, addr) \
    asm volatile("ldmatrix.sync.aligned.m8n8.x4.shared.b16 {%0,%1,%2,%3}, [%4];" \
        : "=r"(r0), "=r"(r1), "=r"(r2), "=r"(r3) : "r"(addr))

#define MMA_F16(d, a, b0, b1) \
    asm volatile("mma.sync.aligned.m16n8k16.row.col.f32.f16.f16.f32 " \
        "{%0,%1,%2,%3}, {%4,%5,%6,%7}, {%8,%9}, {%0,%1,%2,%3};" \
        : "+f"((d)[0]), "+f"((d)[1]), "+f"((d)[2]), "+f"((d)[3]) \
        : "r"((a)[0]), "r"((a)[1]), "r"((a)[2]), "r"((a)[3]), "r"(b0), "r"(b1))

// ================= embedding =================
__global__ void embed_kernel(const int* __restrict__ tok,
                             const float* __restrict__ we,
                             const float* __restrict__ pt,
                             float* __restrict__ x,
                             fp16* __restrict__ xh, fp16* __restrict__ xl)
{
    int m = blockIdx.x;
    int t = tok[m];
    const float* wr = we + (size_t)t * DD;
    const float* pr = pt + (size_t)t * DD;
    size_t base = (size_t)m * DD;
    for (int j = threadIdx.x; j < DD; j += blockDim.x) {
        float v = wr[j] + pr[j];
        x[base + j] = v;
        fp16 h, l; split_fp16(v, h, l);
        xh[base + j] = h; xl[base + j] = l;
    }
}

// ========== weight transpose + fp16 round ==========
__global__ __launch_bounds__(256)
void wsplit_kernel(const float* __restrict__ W, fp16* __restrict__ Th, int K, int N)
{
    __shared__ float s[32][33];
    int nb = blockIdx.x * 32, kb = blockIdx.y * 32;
    int tx = threadIdx.x & 31, ty = threadIdx.x >> 5;
    #pragma unroll
    for (int j = 0; j < 4; j++)
        s[ty + 8*j][tx] = W[(size_t)(kb + ty + 8*j) * N + nb + tx];
    __syncthreads();
    #pragma unroll
    for (int j = 0; j < 4; j++) {
        float v = s[tx][ty + 8*j];
        Th[(size_t)(nb + ty + 8*j) * K + kb + tx] = __float2half_rn(v);
    }
}

__global__ void bcat_kernel(const float* __restrict__ a, const float* __restrict__ b,
                            const float* __restrict__ c, float* __restrict__ dst, int n)
{
    int i = blockIdx.x * blockDim.x + threadIdx.x;
    if (i < n) { dst[i] = a[i]; dst[n + i] = b[i]; dst[2*n + i] = c[i]; }
}

// ================= fp16x2 mma.sync GEMM: BK=64, 2-stage, 2 CTAs/SM =================
// BM in {128,64}. mode 0: fp32+bias; 1: relu->fp16 h/l; 2: +bias+Res->fp32;
// mode 3: QKV: z=0 -> Ch/Cl fp16 split remap, z=1 -> Khp fp16 remap, z=2 -> C fp32 remap.
template<int BM>
__global__ __launch_bounds__(256, 2)
void gemm_kernel(const fp16* __restrict__ Ah, const fp16* __restrict__ Al,
                 const fp16* __restrict__ Bh_,
                 const float* __restrict__ bias_, const float* __restrict__ Res,
                 float* __restrict__ C_, fp16* __restrict__ Ch, fp16* __restrict__ Cl,
                 fp16* __restrict__ Khp,
                 int K, int N, int mode, size_t zsB, size_t zsBias)
{
    constexpr int SA = BM * 128;            // A array bytes per stage (BM rows x 64 fp16)
    constexpr int SB = 16384;               // B: 128 rows x 64 fp16
    constexpr int STAGE = 2 * SA + SB;
    constexpr int NP = (BM == 128) ? 4 : 2;

    extern __shared__ char smem[];
    const uint32_t sb = smem_u32(smem);
    const int tid = threadIdx.x;
    const int lane = tid & 31, wid = tid >> 5;
    const int WM = (BM == 128) ? (wid & 3) : (wid & 1);
    const int WN = (BM == 128) ? (wid >> 2) : (wid >> 1);
    const int m0 = blockIdx.y * BM, n0 = blockIdx.x * 128;

    const fp16* Bh = Bh_ + blockIdx.z * zsB;
    const float* bias = bias_ + blockIdx.z * zsBias;

    // loader mapping: row = tid>>3 (+32 per t-step), kg = tid&7 (16B group)
    const int lrow = tid >> 3, lkg = tid & 7;
    const uint32_t so = (uint32_t)(lrow * 128 + ((lkg ^ (lrow & 7)) << 4));
    const fp16* gAh0 = Ah + (size_t)(m0 + lrow) * K + lkg * 8;
    const fp16* gAl0 = Al + (size_t)(m0 + lrow) * K + lkg * 8;
    const fp16* gBh0 = Bh + (size_t)(n0 + lrow) * K + lkg * 8;

    // ldmatrix offsets
    int matA = lane >> 3;
    int arow_local = ((matA & 1) << 3) + (lane & 7);
    int akgbit = matA >> 1;
    uint32_t offA[2][4];
    #pragma unroll
    for (int mt = 0; mt < 2; mt++) {
        int row = WM * 32 + mt * 16 + arow_local;
        #pragma unroll
        for (int ks = 0; ks < 4; ks++)
            offA[mt][ks] = (uint32_t)(row * 128 + (((ks * 2 + akgbit) ^ (row & 7)) << 4));
    }
    int brow_local = ((matA >> 1) << 3) + (lane & 7);
    int bkgbit = matA & 1;
    uint32_t offB[NP][4];
    #pragma unroll
    for (int np = 0; np < NP; np++) {
        int row = WN * (NP * 16) + np * 16 + brow_local;
        #pragma unroll
        for (int ks = 0; ks < 4; ks++)
            offB[np][ks] = (uint32_t)(row * 128 + (((ks * 2 + bkgbit) ^ (row & 7)) << 4));
    }

    float acc[2][2*NP][4];
    #pragma unroll
    for (int i = 0; i < 2; i++)
        #pragma unroll
        for (int j = 0; j < 2*NP; j++)
            #pragma unroll
            for (int qq = 0; qq < 4; qq++) acc[i][j][qq] = 0.f;

    const int NC = K >> 6;

    auto load_stage = [&](int stage, int chunk) {
        uint32_t base = sb + stage * STAGE;
        size_t gk = (size_t)(chunk << 6);
        #pragma unroll
        for (int t = 0; t < BM/32; t++) {
            CP_ASYNC16(base       + so + 4096u*t, gAh0 + (size_t)(32*t) * K + gk);
            CP_ASYNC16(base + SA  + so + 4096u*t, gAl0 + (size_t)(32*t) * K + gk);
        }
        #pragma unroll
        for (int t = 0; t < 4; t++)
            CP_ASYNC16(base + 2*SA + so + 4096u*t, gBh0 + (size_t)(32*t) * K + gk);
    };

    load_stage(0, 0); CP_COMMIT();

    for (int i = 0; i < NC; i++) {
        if (i + 1 < NC) {
            load_stage((i + 1) & 1, i + 1);
            CP_COMMIT();
            CP_WAIT1();
        } else {
            CP_WAIT0();
        }
        __syncthreads();

        uint32_t base = sb + (i & 1) * STAGE;
        uint32_t sAh = base, sAl = base + SA, sBh = base + 2*SA;

        #pragma unroll
        for (int ks = 0; ks < 4; ks++) {
            uint32_t ah[2][4], al[2][4];
            #pragma unroll
            for (int mt = 0; mt < 2; mt++) {
                LDSM_X4(ah[mt][0], ah[mt][1], ah[mt][2], ah[mt][3], sAh + offA[mt][ks]);
                LDSM_X4(al[mt][0], al[mt][1], al[mt][2], al[mt][3], sAl + offA[mt][ks]);
            }
            #pragma unroll
            for (int np = 0; np < NP; np++) {
                uint32_t bh[4];
                LDSM_X4(bh[0], bh[1], bh[2], bh[3], sBh + offB[np][ks]);
                #pragma unroll
                for (int mt = 0; mt < 2; mt++) {
                    MMA_F16(acc[mt][np*2+0], ah[mt], bh[0], bh[1]);
                    MMA_F16(acc[mt][np*2+0], al[mt], bh[0], bh[1]);
                    MMA_F16(acc[mt][np*2+1], ah[mt], bh[2], bh[3]);
                    MMA_F16(acc[mt][np*2+1], al[mt], bh[2], bh[3]);
                }
            }
        }
        __syncthreads();
    }

    // -------- epilogue --------
    #pragma unroll
    for (int mt = 0; mt < 2; mt++) {
        int r0 = m0 + WM * 32 + mt * 16 + (lane >> 2);
        int r1 = r0 + 8;
        #pragma unroll
        for (int nt = 0; nt < 2*NP; nt++) {
            int c = n0 + WN * (NP * 16) + nt * 8 + ((lane & 3) << 1);
            float2 bv = *(const float2*)(bias + c);
            float v00 = acc[mt][nt][0] + bv.x, v01 = acc[mt][nt][1] + bv.y;
            float v10 = acc[mt][nt][2] + bv.x, v11 = acc[mt][nt][3] + bv.y;
            if (mode == 0) {
                *(float2*)(C_ + (size_t)r0 * N + c) = make_float2(v00, v01);
                *(float2*)(C_ + (size_t)r1 * N + c) = make_float2(v10, v11);
            } else if (mode == 1) {
                v00 = fmaxf(v00, 0.f); v01 = fmaxf(v01, 0.f);
                v10 = fmaxf(v10, 0.f); v11 = fmaxf(v11, 0.f);
                fp16 h0,l0,h1,l1,h2,l2,h3,l3;
                split_fp16(v00,h0,l0); split_fp16(v01,h1,l1);
                split_fp16(v10,h2,l2); split_fp16(v11,h3,l3);
                *(__half2*)(Ch + (size_t)r0 * N + c) = __halves2half2(h0, h1);
                *(__half2*)(Cl + (size_t)r0 * N + c) = __halves2half2(l0, l1);
                *(__half2*)(Ch + (size_t)r1 * N + c) = __halves2half2(h2, h3);
                *(__half2*)(Cl + (size_t)r1 * N + c) = __halves2half2(l2, l3);
            } else if (mode == 2) {
                float2 q0 = *(const float2*)(Res + (size_t)r0 * N + c);
                float2 q1 = *(const float2*)(Res + (size_t)r1 * N + c);
                *(float2*)(C_ + (size_t)r0 * N + c) = make_float2(v00 + q0.x, v01 + q0.y);
                *(float2*)(C_ + (size_t)r1 * N + c) = make_float2(v10 + q1.x, v11 + q1.y);
            } else {
                int b0_ = r0 >> 9, s0_ = r0 & 511;
                int b1_ = r1 >> 9, s1_ = r1 & 511;
                int h_ = c >> 6, d_ = c & 63;
                size_t i0 = ((((size_t)b0_ * HH + h_) * SS + s0_) << 6) + d_;
                size_t i1 = ((((size_t)b1_ * HH + h_) * SS + s1_) << 6) + d_;
                int z = blockIdx.z;
                if (z == 0) {
                    fp16 h0,l0,h1,l1,h2,l2,h3,l3;
                    split_fp16(v00,h0,l0); split_fp16(v01,h1,l1);
                    split_fp16(v10,h2,l2); split_fp16(v11,h3,l3);
                    *(__half2*)(Ch + i0) = __halves2half2(h0, h1);
                    *(__half2*)(Cl + i0) = __halves2half2(l0, l1);
                    *(__half2*)(Ch + i1) = __halves2half2(h2, h3);
                    *(__half2*)(Cl + i1) = __halves2half2(l2, l3);
                } else if (z == 1) {
                    *(__half2*)(Khp + i0) = __halves2half2(__float2half_rn(v00), __float2half_rn(v01));
                    *(__half2*)(Khp + i1) = __halves2half2(__float2half_rn(v10), __float2half_rn(v11));
                } else {
                    *(float2*)(C_ + i0) = make_float2(v00, v01);
                    *(float2*)(C_ + i1) = make_float2(v10, v11);
                }
            }
        }
    }
}

// ================= fused attention: tensor-core scores + fp32 softmax/AV =================
#define SC_B   0
#define RA_B   (32*513*4)              // 65664
#define RB_B   (RA_B + 24576)          // 90240
#define ATT_SMEM (RB_B + 17408)        // 107648

__global__ __launch_bounds__(256, 2)
void attn_kernel(const fp16* __restrict__ qh, const fp16* __restrict__ ql,
                 const fp16* __restrict__ kh, const float* __restrict__ v,
                 const int* __restrict__ tok,
                 float* __restrict__ probs, fp16* __restrict__ avh, fp16* __restrict__ avl)
{
    extern __shared__ char smc[];
    float* sm = (float*)smc;
    float* sc = sm;                        // 32 x 513
    const uint32_t sb = smem_u32(smc);
    int qb = blockIdx.x, h = blockIdx.y, b = blockIdx.z;
    int tid = threadIdx.x;
    int w = tid >> 5, lane = tid & 31;

    const size_t bh_off = (((size_t)b * HH + h) * SS) << 6;
    const fp16* qh_g = qh + bh_off + ((size_t)qb * 32 << 6);
    const fp16* ql_g = ql + bh_off + ((size_t)qb * 32 << 6);
    const fp16* kh_g = kh + bh_off;
    const float* v_g = v + bh_off;
    const int* tb = tok + b * SS;

    auto pf_k = [&](int ch, int buf) {
        uint32_t sdst = sb + RA_B + 8192 + buf * 8192;
        const fp16* src = kh_g + (size_t)(ch * 64) * 64;
        #pragma unroll
        for (int t = 0; t < 2; t++) {
            int j = tid + 256 * t;
            int row = j >> 3, kg = j & 7;
            CP_ASYNC16(sdst + (uint32_t)(row * 128 + ((kg ^ (row & 7)) << 4)),
                       src + (size_t)row * 64 + kg * 8);
        }
    };
    {
        int row = tid >> 3, kg = tid & 7;
        uint32_t so = (uint32_t)(row * 128 + ((kg ^ (row & 7)) << 4));
        CP_ASYNC16(sb + RA_B + so,        qh_g + (size_t)row * 64 + kg * 8);
        CP_ASYNC16(sb + RA_B + 4096 + so, ql_g + (size_t)row * 64 + kg * 8);
    }
    pf_k(0, 0);
    CP_COMMIT();

    int qh16 = (w >> 2) * 16;
    int keyq = w & 3;
    int matA = lane >> 3;
    int arow = qh16 + ((matA & 1) << 3) + (lane & 7);
    int akg = matA >> 1;
    uint32_t offQ[4];
    #pragma unroll
    for (int ks = 0; ks < 4; ks++)
        offQ[ks] = (uint32_t)(arow * 128 + (((ks * 2 + akg) ^ (arow & 7)) << 4));
    int brow = keyq * 16 + ((matA >> 1) << 3) + (lane & 7);
    int bkg = matA & 1;
    uint32_t offK[4];
    #pragma unroll
    for (int ks = 0; ks < 4; ks++)
        offK[ks] = (uint32_t)(brow * 128 + (((ks * 2 + bkg) ^ (brow & 7)) << 4));

    const uint32_t qhb = sb + RA_B, qlb = sb + RA_B + 4096;

    for (int ch = 0; ch < 8; ch++) {
        if (ch < 7) pf_k(ch + 1, (ch + 1) & 1);
        CP_COMMIT();
        CP_WAIT1();
        __syncthreads();
        uint32_t kb = sb + RA_B + 8192 + (ch & 1) * 8192;

        float c0[4] = {0.f,0.f,0.f,0.f}, c1[4] = {0.f,0.f,0.f,0.f};
        #pragma unroll
        for (int ks = 0; ks < 4; ks++) {
            uint32_t ah[4], al[4], bbv[4];
            LDSM_X4(ah[0], ah[1], ah[2], ah[3], qhb + offQ[ks]);
            LDSM_X4(al[0], al[1], al[2], al[3], qlb + offQ[ks]);
            LDSM_X4(bbv[0], bbv[1], bbv[2], bbv[3], kb + offK[ks]);
            MMA_F16(c0, ah, bbv[0], bbv[1]);
            MMA_F16(c0, al, bbv[0], bbv[1]);
            MMA_F16(c1, ah, bbv[2], bbv[3]);
            MMA_F16(c1, al, bbv[2], bbv[3]);
        }
        int tc = lane >> 2, tcol = (lane & 3) * 2;
        int q0 = qh16 + tc, q1 = q0 + 8;
        #pragma unroll
        for (int nt = 0; nt < 2; nt++) {
            float* cc = nt ? c1 : c0;
            int key0 = ch * 64 + keyq * 16 + nt * 8 + tcol;
            bool m0 = (tb[key0] == 0), m1 = (tb[key0 + 1] == 0);
            sc[q0 * 513 + key0]     = m0 ? -INFINITY : cc[0] * 0.125f;
            sc[q0 * 513 + key0 + 1] = m1 ? -INFINITY : cc[1] * 0.125f;
            sc[q1 * 513 + key0]     = m0 ? -INFINITY : cc[2] * 0.125f;
            sc[q1 * 513 + key0 + 1] = m1 ? -INFINITY : cc[3] * 0.125f;
        }
        __syncthreads();
    }

    auto pf_v = [&](const float* gsrc, int buf) {
        uint32_t sdst = sb + (buf ? RB_B : RA_B);
        #pragma unroll
        for (int t = 0; t < 4; t++) {
            int j = tid + 256 * t;
            int row = j >> 4, c4 = j & 15;
            CP_ASYNC16(sdst + (uint32_t)(row * 68 + c4 * 4) * 4,
                       gsrc + (size_t)row * 64 + c4 * 4);
        }
    };
    pf_v(v_g, 0); CP_COMMIT();

    #pragma unroll 1
    for (int rr = 0; rr < 4; rr++) {
        int row = w * 4 + rr;
        float* srow = sc + row * 513;
        float m = -INFINITY;
        for (int j = lane; j < 512; j += 32) m = fmaxf(m, srow[j]);
        #pragma unroll
        for (int o = 16; o > 0; o >>= 1) m = fmaxf(m, __shfl_xor_sync(~0u, m, o));
        float sum = 0.f;
        for (int j = lane; j < 512; j += 32) {
            float e = __expf(srow[j] - m);
            srow[j] = e; sum += e;
        }
        #pragma unroll
        for (int o = 16; o > 0; o >>= 1) sum += __shfl_xor_sync(~0u, sum, o);
        float inv = 1.f / sum;
        float* prow = probs + ((((size_t)b * HH + h) * SS + qb * 32 + row) << 9);
        for (int j = lane; j < 512; j += 32) {
            float p = srow[j] * inv;
            srow[j] = p;
            prow[j] = p;
        }
    }
    __syncthreads();

    int ql_ = tid & 31, dg = tid >> 5;
    float a8[8] = {};
    for (int ch = 0; ch < 8; ch++) {
        if (ch < 7) pf_v(v_g + (size_t)(ch + 1) * 64 * 64, (ch + 1) & 1);
        CP_COMMIT();
        CP_WAIT1();
        __syncthreads();
        const float* kvb = sm + ((ch & 1) ? (RB_B >> 2) : (RA_B >> 2));
        const float* srow = sc + ql_ * 513 + ch * 64;
        #pragma unroll 4
        for (int kk = 0; kk < 64; kk++) {
            float s = srow[kk];
            float4 v0 = *(const float4*)(kvb + kk * 68 + dg * 8);
            float4 v1 = *(const float4*)(kvb + kk * 68 + dg * 8 + 4);
            a8[0] = fmaf(s, v0.x, a8[0]); a8[1] = fmaf(s, v0.y, a8[1]);
            a8[2] = fmaf(s, v0.z, a8[2]); a8[3] = fmaf(s, v0.w, a8[3]);
            a8[4] = fmaf(s, v1.x, a8[4]); a8[5] = fmaf(s, v1.y, a8[5]);
            a8[6] = fmaf(s, v1.z, a8[6]); a8[7] = fmaf(s, v1.w, a8[7]);
        }
        __syncthreads();
    }
    size_t o = ((size_t)(b * SS + qb * 32 + ql_) << 10) + h * 64 + dg * 8;
    uint32_t ph[4], pl[4];
    #pragma unroll
    for (int i = 0; i < 4; i++) {
        fp16 h0, l0, h1, l1;
        split_fp16(a8[2*i], h0, l0);
        split_fp16(a8[2*i+1], h1, l1);
        ph[i] = ((uint32_t)__half_as_ushort(h1) << 16) | __half_as_ushort(h0);
        pl[i] = ((uint32_t)__half_as_ushort(l1) << 16) | __half_as_ushort(l0);
    }
    *(uint4*)(avh + o) = make_uint4(ph[0], ph[1], ph[2], ph[3]);
    *(uint4*)(avl + o) = make_uint4(pl[0], pl[1], pl[2], pl[3]);
}

// ================= layernorm + fp16 split =================
__global__ __launch_bounds__(256)
void ln_kernel(const float* __restrict__ in, float* __restrict__ out,
               fp16* __restrict__ oh, fp16* __restrict__ ol)
{
    int row = blockIdx.x;
    int tid = threadIdx.x;
    const float* r = in + (size_t)row * DD;
    float v0 = r[tid], v1 = r[tid + 256], v2 = r[tid + 512], v3 = r[tid + 768];
    float s = v0 + v1 + v2 + v3;

    __shared__ float sh[32];
    #pragma unroll
    for (int o = 16; o > 0; o >>= 1) s += __shfl_down_sync(~0u, s, o);
    if ((tid & 31) == 0) sh[tid >> 5] = s;
    __syncthreads();
    if (tid < 8) {
        s = sh[tid];
        #pragma unroll
        for (int o = 4; o > 0; o >>= 1) s += __shfl_down_sync(0xffu, s, o);
        if (tid == 0) sh[0] = s;
    }
    __syncthreads();
    float mean = sh[0] * (1.f / 1024.f);
    float d0 = v0 - mean, d1 = v1 - mean, d2 = v2 - mean, d3 = v3 - mean;
    float qv = d0*d0 + d1*d1 + d2*d2 + d3*d3;
    __syncthreads();
    #pragma unroll
    for (int o = 16; o > 0; o >>= 1) qv += __shfl_down_sync(~0u, qv, o);
    if ((tid & 31) == 0) sh[tid >> 5] = qv;
    __syncthreads();
    if (tid < 8) {
        qv = sh[tid];
        #pragma unroll
        for (int o = 4; o > 0; o >>= 1) qv += __shfl_down_sync(0xffu, qv, o);
        if (tid == 0) sh[0] = qv;
    }
    __syncthreads();
    float inv = rsqrtf(sh[0] * (1.f / 1024.f) + 1e-5f);
    size_t base = (size_t)row * DD;
    #pragma unroll
    for (int jj = 0; jj < 4; jj++) {
        float d = (jj == 0 ? d0 : jj == 1 ? d1 : jj == 2 ? d2 : d3);
        float val = d * inv;
        int idx = tid + jj * 256;
        out[base + idx] = val;
        fp16 h, l; split_fp16(val, h, l);
        oh[base + idx] = h; ol[base + idx] = l;
    }
}

// ================= host driver =================
extern "C" void kernel_launch(void* const* d_in, const int* in_sizes, int n_in,
                              void* d_out, int out_size)
{
    const int*   tok = (const int*)d_in[0];
    const float* we  = (const float*)d_in[1];
    const float* pt  = (const float*)d_in[2];
    const float* Wq  = (const float*)d_in[3];  const float* bq = (const float*)d_in[4];
    const float* Wk  = (const float*)d_in[5];  const float* bk = (const float*)d_in[6];
    const float* Wv  = (const float*)d_in[7];  const float* bv = (const float*)d_in[8];
    const float* Wo  = (const float*)d_in[9];  const float* bo = (const float*)d_in[10];
    const float* W1  = (const float*)d_in[11]; const float* b1 = (const float*)d_in[12];
    const float* W2  = (const float*)d_in[13]; const float* b2 = (const float*)d_in[14];
    float* out = (float*)d_out;

    float *x, *yp, *x1p, *bqkv, *vf;
    fp16 *xh, *xl, *qhp, *qlp, *khp, *avh, *avl, *x1h, *x1l, *ffh, *ffl;
    cudaGetSymbolAddress((void**)&x,   g_x);
    cudaGetSymbolAddress((void**)&xh,  g_xh);  cudaGetSymbolAddress((void**)&xl,  g_xl);
    cudaGetSymbolAddress((void**)&qhp, g_qh);  cudaGetSymbolAddress((void**)&qlp, g_ql);
    cudaGetSymbolAddress((void**)&khp, g_kh);  cudaGetSymbolAddress((void**)&vf,  g_v);
    cudaGetSymbolAddress((void**)&avh, g_avh); cudaGetSymbolAddress((void**)&avl, g_avl);
    cudaGetSymbolAddress((void**)&yp,  g_y);
    cudaGetSymbolAddress((void**)&x1p, g_x1);
    cudaGetSymbolAddress((void**)&x1h, g_x1h); cudaGetSymbolAddress((void**)&x1l, g_x1l);
    cudaGetSymbolAddress((void**)&ffh, g_ffh); cudaGetSymbolAddress((void**)&ffl, g_ffl);
    cudaGetSymbolAddress((void**)&bqkv, g_bqkv);

    fp16 *wqkvT, *woT, *w1T, *w2T;
    cudaGetSymbolAddress((void**)&wqkvT, g_wqkvT);
    cudaGetSymbolAddress((void**)&woT, g_woT);
    cudaGetSymbolAddress((void**)&w1T, g_w1T);
    cudaGetSymbolAddress((void**)&w2T, g_w2T);

    const int GS128 = 2 * (2 * 128 * 128 + 16384);   // 98304
    const int GS64  = 2 * (2 * 64 * 128 + 16384);    // 65536
    cudaFuncSetAttribute(gemm_kernel<128>, cudaFuncAttributeMaxDynamicSharedMemorySize, GS128);
    cudaFuncSetAttribute(gemm_kernel<64>,  cudaFuncAttributeMaxDynamicSharedMemorySize, GS64);
    cudaFuncSetAttribute(attn_kernel, cudaFuncAttributeMaxDynamicSharedMemorySize, ATT_SMEM);

    static cudaStream_t s2 = nullptr;
    static cudaEvent_t eFork = nullptr, eLay[LL];
    if (!s2) {
        cudaStreamCreate(&s2);
        cudaEventCreateWithFlags(&eFork, cudaEventDisableTiming);
        for (int l = 0; l < LL; l++) cudaEventCreateWithFlags(&eLay[l], cudaEventDisableTiming);
    }

    const size_t PROJ = (size_t)DD * DD;
    const size_t WQKV = (size_t)LL * DD * DD;
    const size_t W1SZ = (size_t)DD * DFF;
    const size_t W2SZ = (size_t)DFF * DD;
    const size_t CORR = (size_t)BB * HH * SS * SS;

    auto split_layer = [&](int l, cudaStream_t st) {
        dim3 gP(DD/32, DD/32);
        wsplit_kernel<<<gP, 256, 0, st>>>(Wq + l*PROJ, wqkvT + l*PROJ,          DD, DD);
        wsplit_kernel<<<gP, 256, 0, st>>>(Wk + l*PROJ, wqkvT + WQKV + l*PROJ,   DD, DD);
        wsplit_kernel<<<gP, 256, 0, st>>>(Wv + l*PROJ, wqkvT + 2*WQKV + l*PROJ, DD, DD);
        wsplit_kernel<<<gP, 256, 0, st>>>(Wo + l*PROJ, woT + l*PROJ, DD, DD);
        dim3 g1(DFF/32, DD/32);
        wsplit_kernel<<<g1, 256, 0, st>>>(W1 + l*W1SZ, w1T + l*W1SZ, DD, DFF);
        dim3 g2(DD/32, DFF/32);
        wsplit_kernel<<<g2, 256, 0, st>>>(W2 + l*W2SZ, w2T + l*W2SZ, DFF, DD);
    };

    bcat_kernel<<<(LL*DD + 255)/256, 256>>>(bq, bk, bv, bqkv, LL*DD);
    split_layer(0, (cudaStream_t)0);
    embed_kernel<<<MTOK, 256>>>(tok, we, pt, x, xh, xl);

    cudaEventRecord(eFork, (cudaStream_t)0);
    cudaStreamWaitEvent(s2, eFork, 0);
    for (int l = 1; l < LL; l++) {
        split_layer(l, s2);
        cudaEventRecord(eLay[l], s2);
    }

    dim3 gQKV(DD / 128, MTOK / 64, 3);    // (8,32,3) = 768 CTAs, BM=64
    dim3 gFF (DFF / 128, MTOK / 128);     // (32,16), BM=128
    dim3 gD64(DD / 128, MTOK / 64);       // (8,32) = 256 CTAs, BM=64
    dim3 gA  (SS / 32, HH, BB);           // (16,16,4)

    for (int l = 0; l < LL; l++) {
        if (l > 0) cudaStreamWaitEvent((cudaStream_t)0, eLay[l], 0);

        gemm_kernel<64><<<gQKV, 256, GS64>>>(xh, xl, wqkvT + l*PROJ,
                                          bqkv + l*DD, nullptr, vf, qhp, qlp, khp,
                                          DD, DD, 3, WQKV, (size_t)LL*DD);

        float* probs_l = out + (size_t)MTOK * DD + (size_t)l * CORR;
        attn_kernel<<<gA, 256, ATT_SMEM>>>(qhp, qlp, khp, vf, tok, probs_l, avh, avl);

        gemm_kernel<64><<<gD64, 256, GS64>>>(avh, avl, woT + l*PROJ, bo + l*DD,
                                        x, yp, nullptr, nullptr, nullptr, DD, DD, 2, 0, 0);
        ln_kernel<<<MTOK, 256>>>(yp, x1p, x1h, x1l);

        gemm_kernel<128><<<gFF, 256, GS128>>>(x1h, x1l, w1T + l*W1SZ, b1 + l*DFF,
                                         nullptr, nullptr, ffh, ffl, nullptr, DD, DFF, 1, 0, 0);
        gemm_kernel<64><<<gD64, 256, GS64>>>(ffh, ffl, w2T + l*W2SZ, b2 + l*DD,
                                        x1p, yp, nullptr, nullptr, nullptr, DFF, DD, 2, 0, 0);

        float* xdst = (l == LL - 1) ? out : x;
        ln_kernel<<<MTOK, 256>>>(yp, xdst, xh, xl);
    }
}